// round 1
// baseline (speedup 1.0000x reference)
#include <cuda_runtime.h>

#define NN 4096
#define DD 256
#define MARGIN 0.1f

#define BM 128
#define BN 128
#define BK 16

// ---- device-global scratch (no allocations allowed) ----
__device__ double g_vt_sum;
__device__ double g_tv_sum;
__device__ int    g_cnt[NN];
__device__ float  g_diag[NN];

// ---------------------------------------------------------------------------
// Kernel 1: zero accumulators + compute diag[i] = <v_i, t_i>
// ---------------------------------------------------------------------------
__global__ void diag_init_kernel(const float* __restrict__ V,
                                 const float* __restrict__ T) {
    int i = blockIdx.x * blockDim.x + threadIdx.x;
    if (i == 0) { g_vt_sum = 0.0; g_tv_sum = 0.0; }
    if (i < NN) {
        const float4* v = reinterpret_cast<const float4*>(V + (size_t)i * DD);
        const float4* t = reinterpret_cast<const float4*>(T + (size_t)i * DD);
        float acc = 0.f;
        #pragma unroll
        for (int k = 0; k < DD / 4; k++) {
            float4 a = v[k];
            float4 b = t[k];
            acc += a.x * b.x + a.y * b.y + a.z * b.z + a.w * b.w;
        }
        g_diag[i] = acc;
        g_cnt[i]  = 0;
    }
}

// ---------------------------------------------------------------------------
// Kernel 2: fused SGEMM + ranking epilogue.
// Tile: 128x128, BK=16, 256 threads, 8x8 per-thread micro-tile.
// Epilogue (per element s = S[r,c], r != c):
//   vt += max(0, MARGIN - diag[r] + s)
//   tv += max(0, MARGIN - diag[c] + s)
//   cnt[r] += (s > diag[r])
// ---------------------------------------------------------------------------
__global__ __launch_bounds__(256, 2)
void gemm_fused_kernel(const float* __restrict__ V,
                       const float* __restrict__ T) {
    __shared__ float As[BK][BM + 4];
    __shared__ float Bs[BK][BN + 4];
    __shared__ int   s_cnt[BM];

    const int tid  = threadIdx.x;
    const int tx   = tid & 15;   // column group (0..15)
    const int ty   = tid >> 4;   // row group (0..15)
    const int row0 = blockIdx.y * BM;
    const int col0 = blockIdx.x * BN;

    float acc[8][8];
    #pragma unroll
    for (int i = 0; i < 8; i++)
        #pragma unroll
        for (int j = 0; j < 8; j++)
            acc[i][j] = 0.f;

    for (int k0 = 0; k0 < DD; k0 += BK) {
        // Cooperative load: 128 rows x 16 cols (= 512 float4) per matrix.
        #pragma unroll
        for (int l = 0; l < 2; l++) {
            int idx = tid + l * 256;          // 0..511
            int r   = idx >> 2;               // 0..127
            int c4  = (idx & 3) << 2;         // {0,4,8,12}
            float4 a = *reinterpret_cast<const float4*>(
                V + (size_t)(row0 + r) * DD + k0 + c4);
            As[c4 + 0][r] = a.x;
            As[c4 + 1][r] = a.y;
            As[c4 + 2][r] = a.z;
            As[c4 + 3][r] = a.w;
            float4 b = *reinterpret_cast<const float4*>(
                T + (size_t)(col0 + r) * DD + k0 + c4);
            Bs[c4 + 0][r] = b.x;
            Bs[c4 + 1][r] = b.y;
            Bs[c4 + 2][r] = b.z;
            Bs[c4 + 3][r] = b.w;
        }
        __syncthreads();

        #pragma unroll
        for (int k = 0; k < BK; k++) {
            float a_reg[8], b_reg[8];
            #pragma unroll
            for (int i = 0; i < 8; i++) a_reg[i] = As[k][ty * 8 + i];
            #pragma unroll
            for (int j = 0; j < 8; j++) b_reg[j] = Bs[k][tx * 8 + j];
            #pragma unroll
            for (int i = 0; i < 8; i++)
                #pragma unroll
                for (int j = 0; j < 8; j++)
                    acc[i][j] += a_reg[i] * b_reg[j];
        }
        __syncthreads();
    }

    // ---- fused epilogue ----
    float dr[8], dc[8];
    int cnt_local[8];
    #pragma unroll
    for (int i = 0; i < 8; i++) {
        dr[i] = g_diag[row0 + ty * 8 + i];
        cnt_local[i] = 0;
    }
    #pragma unroll
    for (int j = 0; j < 8; j++) dc[j] = g_diag[col0 + tx * 8 + j];

    float vt = 0.f, tv = 0.f;
    #pragma unroll
    for (int i = 0; i < 8; i++) {
        const int r = row0 + ty * 8 + i;
        #pragma unroll
        for (int j = 0; j < 8; j++) {
            const int c = col0 + tx * 8 + j;
            const float s = acc[i][j];
            if (r != c) {
                vt += fmaxf(0.f, MARGIN - dr[i] + s);
                tv += fmaxf(0.f, MARGIN - dc[j] + s);
                cnt_local[i] += (s > dr[i]) ? 1 : 0;
            }
        }
    }

    // per-row rank counts: shared accumulate, one global atomic per row
    if (tid < BM) s_cnt[tid] = 0;
    __syncthreads();
    #pragma unroll
    for (int i = 0; i < 8; i++)
        if (cnt_local[i]) atomicAdd(&s_cnt[ty * 8 + i], cnt_local[i]);
    __syncthreads();
    if (tid < BM) {
        int c = s_cnt[tid];
        if (c) atomicAdd(&g_cnt[row0 + tid], c);
    }

    // loss sums: warp shuffle reduce, one double atomic per warp
    #pragma unroll
    for (int off = 16; off > 0; off >>= 1) {
        vt += __shfl_down_sync(0xFFFFFFFFu, vt, off);
        tv += __shfl_down_sync(0xFFFFFFFFu, tv, off);
    }
    if ((tid & 31) == 0) {
        atomicAdd(&g_vt_sum, (double)vt);
        atomicAdd(&g_tv_sum, (double)tv);
    }
}

// ---------------------------------------------------------------------------
// Kernel 3: finalize — recalls, mean rank, normalized losses -> d_out[6]
// Output order: (vt_loss, tv_loss, recall1, recall5, recall10, mean_rk)
// ---------------------------------------------------------------------------
__global__ void finalize_kernel(float* __restrict__ out) {
    __shared__ int sA[256], sB[256], sC[256], sD[256];
    const int tid = threadIdx.x;

    int c1 = 0, c5 = 0, c10 = 0, rs = 0;
    for (int i = tid; i < NN; i += 256) {
        int c = g_cnt[i];
        c1  += (c < 1);
        c5  += (c < 5);
        c10 += (c < 10);
        rs  += c;
    }
    sA[tid] = c1; sB[tid] = c5; sC[tid] = c10; sD[tid] = rs;
    __syncthreads();
    for (int s = 128; s > 0; s >>= 1) {
        if (tid < s) {
            sA[tid] += sA[tid + s];
            sB[tid] += sB[tid + s];
            sC[tid] += sC[tid + s];
            sD[tid] += sD[tid + s];
        }
        __syncthreads();
    }
    if (tid == 0) {
        const double denom = (double)NN * (double)(NN - 1);
        out[0] = (float)(g_vt_sum / denom);
        out[1] = (float)(g_tv_sum / denom);
        out[2] = (float)sA[0] / (float)NN;
        out[3] = (float)sB[0] / (float)NN;
        out[4] = (float)sC[0] / (float)NN;
        out[5] = (float)sD[0] / (float)NN;
    }
}

// ---------------------------------------------------------------------------
extern "C" void kernel_launch(void* const* d_in, const int* in_sizes, int n_in,
                              void* d_out, int out_size) {
    (void)in_sizes; (void)n_in; (void)out_size;
    const float* V = (const float*)d_in[0];
    const float* T = (const float*)d_in[1];
    float* out = (float*)d_out;

    diag_init_kernel<<<(NN + 255) / 256, 256>>>(V, T);
    dim3 grid(NN / BN, NN / BM);
    gemm_fused_kernel<<<grid, 256>>>(V, T);
    finalize_kernel<<<1, 256>>>(out);
}

// round 2
// speedup vs baseline: 1.1710x; 1.1710x over previous
#include <cuda_runtime.h>

#define NN 4096
#define DD 256
#define MARGIN 0.1f

#define BM 128
#define BN 128
#define BK 16

typedef unsigned long long u64;

// ---- device-global scratch (no allocations allowed) ----
__device__ double g_vt_sum;
__device__ double g_tv_sum;
__device__ int    g_cnt[NN];
__device__ float  g_diag[NN];

// Packed f32x2 helpers (Blackwell sm_100+)
__device__ __forceinline__ u64 pack2(float lo, float hi) {
    u64 r;
    asm("mov.b64 %0, {%1, %2};" : "=l"(r) : "f"(lo), "f"(hi));
    return r;
}
__device__ __forceinline__ void unpack2(u64 v, float& lo, float& hi) {
    asm("mov.b64 {%0, %1}, %2;" : "=f"(lo), "=f"(hi) : "l"(v));
}
__device__ __forceinline__ void fma2(u64& d, u64 a, u64 b) {
    asm("fma.rn.f32x2 %0, %1, %2, %0;" : "+l"(d) : "l"(a), "l"(b));
}

// ---------------------------------------------------------------------------
// Kernel 1: one warp per row — diag[i] = <v_i, t_i>, zero counters.
// ---------------------------------------------------------------------------
__global__ void diag_init_kernel(const float* __restrict__ V,
                                 const float* __restrict__ T) {
    const int gtid = blockIdx.x * blockDim.x + threadIdx.x;
    const int row  = gtid >> 5;
    const int lane = gtid & 31;
    if (gtid == 0) { g_vt_sum = 0.0; g_tv_sum = 0.0; }
    if (row >= NN) return;

    // each lane handles 8 contiguous floats (2x float4)
    const float4* v = reinterpret_cast<const float4*>(V + (size_t)row * DD) + lane * 2;
    const float4* t = reinterpret_cast<const float4*>(T + (size_t)row * DD) + lane * 2;
    float4 a0 = v[0], a1 = v[1];
    float4 b0 = t[0], b1 = t[1];
    float acc = a0.x * b0.x + a0.y * b0.y + a0.z * b0.z + a0.w * b0.w
              + a1.x * b1.x + a1.y * b1.y + a1.z * b1.z + a1.w * b1.w;
    #pragma unroll
    for (int off = 16; off > 0; off >>= 1)
        acc += __shfl_down_sync(0xFFFFFFFFu, acc, off);
    if (lane == 0) {
        g_diag[row] = acc;
        g_cnt[row]  = 0;
    }
}

// ---------------------------------------------------------------------------
// Kernel 2: fused SGEMM (packed f32x2 FMA) + ranking epilogue.
// Tile: 128x128, BK=16, 256 threads, 8x8 per-thread micro-tile.
// ---------------------------------------------------------------------------
__global__ __launch_bounds__(256, 2)
void gemm_fused_kernel(const float* __restrict__ V,
                       const float* __restrict__ T) {
    __shared__ float As[BK][BM + 4];
    __shared__ float Bs[BK][BN + 4];
    __shared__ int   s_cnt[BM];

    const int tid  = threadIdx.x;
    const int tx   = tid & 15;   // column group (0..15)
    const int ty   = tid >> 4;   // row group (0..15)
    const int row0 = blockIdx.y * BM;
    const int col0 = blockIdx.x * BN;

    u64 acc2[8][4];
    #pragma unroll
    for (int i = 0; i < 8; i++)
        #pragma unroll
        for (int j = 0; j < 4; j++)
            acc2[i][j] = 0ULL;

    for (int k0 = 0; k0 < DD; k0 += BK) {
        // Cooperative load: 128 rows x 16 cols (= 512 float4) per matrix.
        #pragma unroll
        for (int l = 0; l < 2; l++) {
            int idx = tid + l * 256;          // 0..511
            int r   = idx >> 2;               // 0..127
            int c4  = (idx & 3) << 2;         // {0,4,8,12}
            float4 a = *reinterpret_cast<const float4*>(
                V + (size_t)(row0 + r) * DD + k0 + c4);
            As[c4 + 0][r] = a.x;
            As[c4 + 1][r] = a.y;
            As[c4 + 2][r] = a.z;
            As[c4 + 3][r] = a.w;
            float4 b = *reinterpret_cast<const float4*>(
                T + (size_t)(col0 + r) * DD + k0 + c4);
            Bs[c4 + 0][r] = b.x;
            Bs[c4 + 1][r] = b.y;
            Bs[c4 + 2][r] = b.z;
            Bs[c4 + 3][r] = b.w;
        }
        __syncthreads();

        #pragma unroll
        for (int k = 0; k < BK; k++) {
            float4 a0 = *reinterpret_cast<const float4*>(&As[k][ty * 8]);
            float4 a1 = *reinterpret_cast<const float4*>(&As[k][ty * 8 + 4]);
            float4 b0 = *reinterpret_cast<const float4*>(&Bs[k][tx * 8]);
            float4 b1 = *reinterpret_cast<const float4*>(&Bs[k][tx * 8 + 4]);

            u64 bb[4];
            bb[0] = pack2(b0.x, b0.y);
            bb[1] = pack2(b0.z, b0.w);
            bb[2] = pack2(b1.x, b1.y);
            bb[3] = pack2(b1.z, b1.w);

            float av[8] = {a0.x, a0.y, a0.z, a0.w, a1.x, a1.y, a1.z, a1.w};
            #pragma unroll
            for (int i = 0; i < 8; i++) {
                u64 aa = pack2(av[i], av[i]);
                #pragma unroll
                for (int j = 0; j < 4; j++)
                    fma2(acc2[i][j], aa, bb[j]);
            }
        }
        __syncthreads();
    }

    // unpack accumulators
    float acc[8][8];
    #pragma unroll
    for (int i = 0; i < 8; i++)
        #pragma unroll
        for (int j = 0; j < 4; j++)
            unpack2(acc2[i][j], acc[i][2 * j], acc[i][2 * j + 1]);

    // ---- fused epilogue ----
    float dr[8], dc[8];
    int cnt_local[8];
    #pragma unroll
    for (int i = 0; i < 8; i++) {
        dr[i] = g_diag[row0 + ty * 8 + i];
        cnt_local[i] = 0;
    }
    #pragma unroll
    for (int j = 0; j < 8; j++) dc[j] = g_diag[col0 + tx * 8 + j];

    float vt = 0.f, tv = 0.f;
    #pragma unroll
    for (int i = 0; i < 8; i++) {
        const int r = row0 + ty * 8 + i;
        #pragma unroll
        for (int j = 0; j < 8; j++) {
            const int c = col0 + tx * 8 + j;
            const float s = acc[i][j];
            if (r != c) {
                vt += fmaxf(0.f, MARGIN - dr[i] + s);
                tv += fmaxf(0.f, MARGIN - dc[j] + s);
                cnt_local[i] += (s > dr[i]) ? 1 : 0;
            }
        }
    }

    // per-row rank counts: shared accumulate, one global atomic per row
    if (tid < BM) s_cnt[tid] = 0;
    __syncthreads();
    #pragma unroll
    for (int i = 0; i < 8; i++)
        if (cnt_local[i]) atomicAdd(&s_cnt[ty * 8 + i], cnt_local[i]);
    __syncthreads();
    if (tid < BM) {
        int c = s_cnt[tid];
        if (c) atomicAdd(&g_cnt[row0 + tid], c);
    }

    // loss sums: warp shuffle reduce, one double atomic per warp
    #pragma unroll
    for (int off = 16; off > 0; off >>= 1) {
        vt += __shfl_down_sync(0xFFFFFFFFu, vt, off);
        tv += __shfl_down_sync(0xFFFFFFFFu, tv, off);
    }
    if ((tid & 31) == 0) {
        atomicAdd(&g_vt_sum, (double)vt);
        atomicAdd(&g_tv_sum, (double)tv);
    }
}

// ---------------------------------------------------------------------------
// Kernel 3: finalize — recalls, mean rank, normalized losses -> d_out[6]
// Output order: (vt_loss, tv_loss, recall1, recall5, recall10, mean_rk)
// ---------------------------------------------------------------------------
__global__ void finalize_kernel(float* __restrict__ out) {
    __shared__ int sA[256], sB[256], sC[256], sD[256];
    const int tid = threadIdx.x;

    int c1 = 0, c5 = 0, c10 = 0, rs = 0;
    for (int i = tid; i < NN; i += 256) {
        int c = g_cnt[i];
        c1  += (c < 1);
        c5  += (c < 5);
        c10 += (c < 10);
        rs  += c;
    }
    sA[tid] = c1; sB[tid] = c5; sC[tid] = c10; sD[tid] = rs;
    __syncthreads();
    for (int s = 128; s > 0; s >>= 1) {
        if (tid < s) {
            sA[tid] += sA[tid + s];
            sB[tid] += sB[tid + s];
            sC[tid] += sC[tid + s];
            sD[tid] += sD[tid + s];
        }
        __syncthreads();
    }
    if (tid == 0) {
        const double denom = (double)NN * (double)(NN - 1);
        out[0] = (float)(g_vt_sum / denom);
        out[1] = (float)(g_tv_sum / denom);
        out[2] = (float)sA[0] / (float)NN;
        out[3] = (float)sB[0] / (float)NN;
        out[4] = (float)sC[0] / (float)NN;
        out[5] = (float)sD[0] / (float)NN;
    }
}

// ---------------------------------------------------------------------------
extern "C" void kernel_launch(void* const* d_in, const int* in_sizes, int n_in,
                              void* d_out, int out_size) {
    (void)in_sizes; (void)n_in; (void)out_size;
    const float* V = (const float*)d_in[0];
    const float* T = (const float*)d_in[1];
    float* out = (float*)d_out;

    diag_init_kernel<<<(NN * 32 + 255) / 256, 256>>>(V, T);
    dim3 grid(NN / BN, NN / BM);
    gemm_fused_kernel<<<grid, 256>>>(V, T);
    finalize_kernel<<<1, 256>>>(out);
}

// round 4
// speedup vs baseline: 1.7963x; 1.5340x over previous
#include <cuda_runtime.h>
#include <cuda_bf16.h>
#include <cuda.h>
#include <stdint.h>

#define NN 4096
#define DD 256
#define MARGIN 0.1f
#define EPS 0.005f

// tcgen05 available only on arch-specific targets (sm_100a / sm_103a)
#if defined(__CUDA_ARCH_FEAT_SM103_ALL) || defined(__CUDA_ARCH_FEAT_SM100_ALL)
#define HAS_TCGEN05 1
#else
#define HAS_TCGEN05 0
#endif

// idesc kind::f16: dtype=F32, atype=btype=BF16, N=128, M=128 (cg1)
#define IDESC 0x08200490u

typedef unsigned long long u64;

// ---- device-global scratch (no allocations allowed) ----
__device__ double g_vt_sum;
__device__ double g_tv_sum;
__device__ int    g_cnt[NN];
__device__ float  g_diag[NN];
__device__ __align__(1024) __nv_bfloat16 g_Vhi[NN * DD];
__device__ __align__(1024) __nv_bfloat16 g_Vlo[NN * DD];
__device__ __align__(1024) __nv_bfloat16 g_Thi[NN * DD];
__device__ __align__(1024) __nv_bfloat16 g_Tlo[NN * DD];

// ======================= PTX helpers =======================
__device__ __forceinline__ uint32_t smem_u32(const void* p) {
    uint32_t a;
    asm("{ .reg .u64 t; cvta.to.shared.u64 t, %1; cvt.u32.u64 %0, t; }"
        : "=r"(a) : "l"(p));
    return a;
}

__device__ __forceinline__ u64 pack2(float lo, float hi) {
    u64 r;
    asm("mov.b64 %0, {%1, %2};" : "=l"(r) : "f"(lo), "f"(hi));
    return r;
}
__device__ __forceinline__ void unpack2(u64 v, float& lo, float& hi) {
    asm("mov.b64 {%0, %1}, %2;" : "=f"(lo), "=f"(hi) : "l"(v));
}
__device__ __forceinline__ void fma2(u64& d, u64 a, u64 b) {
    asm("fma.rn.f32x2 %0, %1, %2, %0;" : "+l"(d) : "l"(a), "l"(b));
}

#define MBARRIER_INIT(addr, cnt) \
    asm volatile("mbarrier.init.shared.b64 [%0], %1;" \
        :: "r"((uint32_t)(addr)), "r"((uint32_t)(cnt)) : "memory")

#define MBARRIER_EXPECT_TX(addr, bytes) \
    asm volatile("mbarrier.arrive.expect_tx.shared.b64 _, [%0], %1;" \
        :: "r"((uint32_t)(addr)), "r"((uint32_t)(bytes)) : "memory")

#define MBARRIER_INVAL(addr) \
    asm volatile("mbarrier.inval.shared.b64 [%0];" :: "r"((uint32_t)(addr)) : "memory")

#define MBARRIER_WAIT_PARITY(addr, parity) do {                                   \
    uint32_t _mb = (uint32_t)(addr);                                              \
    uint32_t _ph = (uint32_t)(parity);                                            \
    uint32_t _done;                                                               \
    asm volatile("{\n\t.reg .pred p;\n\t"                                         \
        "mbarrier.try_wait.parity.acquire.cta.shared::cta.b64 p, [%1], %2;\n\t"   \
        "selp.b32 %0, 1, 0, p;\n\t}"                                              \
        : "=r"(_done) : "r"(_mb), "r"(_ph) : "memory");                           \
    if (!_done) {                                                                 \
        asm volatile("{\n\t.reg .pred P1;\n\t"                                    \
            "W_%=:\n\t"                                                           \
            "mbarrier.try_wait.parity.acquire.cta.shared::cta.b64 P1, [%0], %1, 0x989680;\n\t" \
            "@P1 bra.uni D_%=;\n\t"                                               \
            "bra.uni W_%=;\n\t"                                                   \
            "D_%=:\n\t}"                                                          \
            :: "r"(_mb), "r"(_ph) : "memory");                                    \
    }                                                                             \
} while (0)

#if HAS_TCGEN05
#define TCGEN05_ALLOC(res_addr, ncols) \
    asm volatile("tcgen05.alloc.cta_group::1.sync.aligned.shared::cta.b32 [%0], %1;" \
        :: "r"((uint32_t)(res_addr)), "r"((uint32_t)(ncols)) : "memory")
#define TCGEN05_RELINQ() \
    asm volatile("tcgen05.relinquish_alloc_permit.cta_group::1.sync.aligned;")
#define TCGEN05_DEALLOC(tmem, ncols) \
    asm volatile("tcgen05.dealloc.cta_group::1.sync.aligned.b32 %0, %1;" \
        :: "r"(tmem), "r"((uint32_t)(ncols)))
#define TCGEN05_COMMIT(mbar) \
    asm volatile("tcgen05.commit.cta_group::1.mbarrier::arrive::one.shared::cluster.b64 [%0];" \
        :: "r"((uint32_t)(mbar)) : "memory")
#define TCGEN05_FENCE_AFTER() \
    asm volatile("tcgen05.fence::after_thread_sync;" ::: "memory")
#define TCGEN05_FENCE_BEFORE() \
    asm volatile("tcgen05.fence::before_thread_sync;" ::: "memory")
#define TCGEN05_WAIT_LD() \
    asm volatile("tcgen05.wait::ld.sync.aligned;" ::: "memory")

#define TCGEN05_LD_X32(r, addr) \
    asm volatile("tcgen05.ld.sync.aligned.32x32b.x32.b32 " \
        "{%0, %1, %2, %3, %4, %5, %6, %7, %8, %9, %10, %11, %12, %13, %14, %15, " \
        " %16, %17, %18, %19, %20, %21, %22, %23, %24, %25, %26, %27, %28, %29, %30, %31}, [%32];" \
        : "=r"((r)[0]),  "=r"((r)[1]),  "=r"((r)[2]),  "=r"((r)[3]),  \
          "=r"((r)[4]),  "=r"((r)[5]),  "=r"((r)[6]),  "=r"((r)[7]),  \
          "=r"((r)[8]),  "=r"((r)[9]),  "=r"((r)[10]), "=r"((r)[11]), \
          "=r"((r)[12]), "=r"((r)[13]), "=r"((r)[14]), "=r"((r)[15]), \
          "=r"((r)[16]), "=r"((r)[17]), "=r"((r)[18]), "=r"((r)[19]), \
          "=r"((r)[20]), "=r"((r)[21]), "=r"((r)[22]), "=r"((r)[23]), \
          "=r"((r)[24]), "=r"((r)[25]), "=r"((r)[26]), "=r"((r)[27]), \
          "=r"((r)[28]), "=r"((r)[29]), "=r"((r)[30]), "=r"((r)[31]) \
        : "r"(addr))

// SW128 SMEM descriptor: layout=SW128(2), version=1, SBO=64, LBO=1
static __device__ __forceinline__ uint64_t make_desc(uint32_t addr) {
    const uint64_t BASE =
        (uint64_t(2)  << 61) | (uint64_t(1) << 46) |
        (uint64_t(64) << 32) | (uint64_t(1) << 16);
    return BASE | ((uint64_t)(addr >> 4) & 0x3FFF);
}

__device__ __forceinline__ void tma_ld_2d(uint32_t dst, const void* map,
                                          int cx, int cy, uint32_t mbar) {
    asm volatile(
        "cp.async.bulk.tensor.2d.shared::cta.global.tile.mbarrier::complete_tx::bytes "
        "[%0], [%1, {%2, %3}], [%4];"
        :: "r"(dst), "l"(map), "r"(cx), "r"(cy), "r"(mbar) : "memory");
}

__device__ __forceinline__ void mma_f16_ss(uint32_t d, uint64_t da, uint64_t db,
                                           uint32_t en) {
    asm volatile("{\n\t.reg .pred p;\n\tsetp.ne.u32 p, %4, 0;\n\t"
        "tcgen05.mma.cta_group::1.kind::f16 [%0], %1, %2, %3, {%5, %5, %5, %5}, p;\n\t}"
        :: "r"(d), "l"(da), "l"(db), "r"(IDESC), "r"(en), "r"(0u) : "memory");
}
#endif  // HAS_TCGEN05

// ---------------------------------------------------------------------------
// Kernel 1: one warp per row — diag[i] = <v_i, t_i>, zero counters.
// ---------------------------------------------------------------------------
__global__ void diag_init_kernel(const float* __restrict__ V,
                                 const float* __restrict__ T) {
    const int gtid = blockIdx.x * blockDim.x + threadIdx.x;
    const int row  = gtid >> 5;
    const int lane = gtid & 31;
    if (gtid == 0) { g_vt_sum = 0.0; g_tv_sum = 0.0; }
    if (row >= NN) return;
    const float4* v = reinterpret_cast<const float4*>(V + (size_t)row * DD) + lane * 2;
    const float4* t = reinterpret_cast<const float4*>(T + (size_t)row * DD) + lane * 2;
    float4 a0 = v[0], a1 = v[1];
    float4 b0 = t[0], b1 = t[1];
    float acc = a0.x * b0.x + a0.y * b0.y + a0.z * b0.z + a0.w * b0.w
              + a1.x * b1.x + a1.y * b1.y + a1.z * b1.z + a1.w * b1.w;
    #pragma unroll
    for (int off = 16; off > 0; off >>= 1)
        acc += __shfl_down_sync(0xFFFFFFFFu, acc, off);
    if (lane == 0) { g_diag[row] = acc; g_cnt[row] = 0; }
}

// ---------------------------------------------------------------------------
// Kernel 2: fp32 -> bf16 (hi, lo) split, written to device globals.
// ---------------------------------------------------------------------------
#define N4 (NN * DD / 4)

__global__ void convert_kernel(const float* __restrict__ V,
                               const float* __restrict__ T) {
    int i = blockIdx.x * blockDim.x + threadIdx.x;
    const float4* src;
    __nv_bfloat16 *hi, *lo;
    int j = i;
    if (i < N4) { src = (const float4*)V; hi = g_Vhi; lo = g_Vlo; }
    else        { j = i - N4; src = (const float4*)T; hi = g_Thi; lo = g_Tlo; }
    if (j >= N4) return;
    float4 a = src[j];
    __nv_bfloat162 hxy = __floats2bfloat162_rn(a.x, a.y);
    __nv_bfloat162 hzw = __floats2bfloat162_rn(a.z, a.w);
    float2 fxy = __bfloat1622float2(hxy);
    float2 fzw = __bfloat1622float2(hzw);
    __nv_bfloat162 lxy = __floats2bfloat162_rn(a.x - fxy.x, a.y - fxy.y);
    __nv_bfloat162 lzw = __floats2bfloat162_rn(a.z - fzw.x, a.w - fzw.y);
    uint2 h, l;
    h.x = reinterpret_cast<unsigned&>(hxy);
    h.y = reinterpret_cast<unsigned&>(hzw);
    l.x = reinterpret_cast<unsigned&>(lxy);
    l.y = reinterpret_cast<unsigned&>(lzw);
    reinterpret_cast<uint2*>(hi)[j] = h;
    reinterpret_cast<uint2*>(lo)[j] = l;
}

// ---------------------------------------------------------------------------
// Kernel 3: GEMM + fused ranking epilogue.
//   sm_103a cubin: tcgen05 bf16x3 with TMA pipeline (fast path)
//   plain cubin:   FFMA2 shared-memory SGEMM (correct fallback)
// Grid (32, 32); 128 threads.
// ---------------------------------------------------------------------------
#define SMEM_DYN (132672)

__global__ __launch_bounds__(128, 1)
void gemm_tc_kernel(const __grid_constant__ CUtensorMap mVhi,
                    const __grid_constant__ CUtensorMap mVlo,
                    const __grid_constant__ CUtensorMap mThi,
                    const __grid_constant__ CUtensorMap mTlo,
                    const float* __restrict__ V,
                    const float* __restrict__ T) {
    extern __shared__ char smem_raw[];
    const uint32_t raw  = smem_u32(smem_raw);
    const uint32_t base = (raw + 1023) & ~1023u;
    char* gbase = smem_raw + (base - raw);

    const int tid  = threadIdx.x;
    const int lane = tid & 31;
    const int row0 = blockIdx.y * 128;
    const int col0 = blockIdx.x * 128;

#if HAS_TCGEN05
    const int wid = tid >> 5;
    const uint32_t S_TMEMP  = base + 131072;
    const uint32_t MB_FULL0 = base + 131088;
    const uint32_t MB_FULL1 = base + 131096;
    const uint32_t MB_EMPT0 = base + 131104;
    const uint32_t MB_EMPT1 = base + 131112;
    float* s_dc = reinterpret_cast<float*>(gbase + 131136);

    if (wid == 0) {
        TCGEN05_ALLOC(S_TMEMP, 128);
        TCGEN05_RELINQ();
    }
    if (tid == 0) {
        MBARRIER_INIT(MB_FULL0, 1);
        MBARRIER_INIT(MB_FULL1, 1);
        MBARRIER_INIT(MB_EMPT0, 1);
        MBARRIER_INIT(MB_EMPT1, 1);
    }
    __syncthreads();
    uint32_t tmem;
    asm volatile("ld.shared.b32 %0, [%1];" : "=r"(tmem) : "r"(S_TMEMP));

    if (tid == 0) {
        #pragma unroll
        for (int c = 0; c < 2; c++) {
            uint32_t st = base + c * 65536;
            uint32_t mb = c ? MB_FULL1 : MB_FULL0;
            MBARRIER_EXPECT_TX(mb, 65536);
            tma_ld_2d(st +     0, &mVhi, c * 64, row0, mb);
            tma_ld_2d(st + 16384, &mVlo, c * 64, row0, mb);
            tma_ld_2d(st + 32768, &mThi, c * 64, col0, mb);
            tma_ld_2d(st + 49152, &mTlo, c * 64, col0, mb);
        }
        for (int c = 0; c < 4; c++) {
            const int s = c & 1;
            const uint32_t full  = s ? MB_FULL1 : MB_FULL0;
            const uint32_t empty = s ? MB_EMPT1 : MB_EMPT0;
            const uint32_t st    = base + s * 65536;
            MBARRIER_WAIT_PARITY(full, c >> 1);
            const uint64_t dAhi = make_desc(st);
            const uint64_t dAlo = make_desc(st + 16384);
            const uint64_t dBhi = make_desc(st + 32768);
            const uint64_t dBlo = make_desc(st + 49152);
            #pragma unroll
            for (int ks = 0; ks < 4; ks++)
                mma_f16_ss(tmem, dAhi + ks * 2, dBhi + ks * 2,
                           (c == 0 && ks == 0) ? 0u : 1u);
            #pragma unroll
            for (int ks = 0; ks < 4; ks++)
                mma_f16_ss(tmem, dAhi + ks * 2, dBlo + ks * 2, 1u);
            #pragma unroll
            for (int ks = 0; ks < 4; ks++)
                mma_f16_ss(tmem, dAlo + ks * 2, dBhi + ks * 2, 1u);
            TCGEN05_COMMIT(empty);
            if (c < 2) {
                MBARRIER_WAIT_PARITY(empty, 0);
                const int c2 = c + 2;
                MBARRIER_EXPECT_TX(full, 65536);
                tma_ld_2d(st +     0, &mVhi, c2 * 64, row0, full);
                tma_ld_2d(st + 16384, &mVlo, c2 * 64, row0, full);
                tma_ld_2d(st + 32768, &mThi, c2 * 64, col0, full);
                tma_ld_2d(st + 49152, &mTlo, c2 * 64, col0, full);
            }
        }
    }

    s_dc[tid] = g_diag[col0 + tid];

    MBARRIER_WAIT_PARITY(MB_EMPT0, 1);
    MBARRIER_WAIT_PARITY(MB_EMPT1, 1);
    TCGEN05_FENCE_AFTER();
    __syncthreads();

    const int r = row0 + tid;
    const float dr = g_diag[r];
    float vt = 0.f, tv = 0.f;
    int cnt = 0;

    #pragma unroll 1
    for (int g = 0; g < 4; g++) {
        uint32_t dreg[32];
        TCGEN05_LD_X32(dreg, tmem + g * 32);
        TCGEN05_WAIT_LD();
        #pragma unroll
        for (int j = 0; j < 32; j++) {
            const int cc = g * 32 + j;
            const int c  = col0 + cc;
            const float sv = __uint_as_float(dreg[j]);
            if (c != r) {
                vt += fmaxf(0.f, MARGIN - dr + sv);
                tv += fmaxf(0.f, MARGIN - s_dc[cc] + sv);
                const float diff = sv - dr;
                if (fabsf(diff) < EPS) {
                    const float4* a4 = reinterpret_cast<const float4*>(V + (size_t)r * DD);
                    const float4* b4 = reinterpret_cast<const float4*>(T + (size_t)c * DD);
                    float ex = 0.f;
                    #pragma unroll 8
                    for (int k = 0; k < DD / 4; k++) {
                        float4 x = a4[k], y = b4[k];
                        ex += x.x * y.x + x.y * y.y + x.z * y.z + x.w * y.w;
                    }
                    cnt += (ex > dr) ? 1 : 0;
                } else {
                    cnt += (diff > 0.f) ? 1 : 0;
                }
            }
        }
    }
    TCGEN05_FENCE_BEFORE();

    atomicAdd(&g_cnt[r], cnt);
    #pragma unroll
    for (int off = 16; off > 0; off >>= 1) {
        vt += __shfl_down_sync(0xFFFFFFFFu, vt, off);
        tv += __shfl_down_sync(0xFFFFFFFFu, tv, off);
    }
    if (lane == 0) {
        atomicAdd(&g_vt_sum, (double)vt);
        atomicAdd(&g_tv_sum, (double)tv);
    }

    __syncthreads();
    if (tid == 0) {
        MBARRIER_INVAL(MB_FULL0); MBARRIER_INVAL(MB_FULL1);
        MBARRIER_INVAL(MB_EMPT0); MBARRIER_INVAL(MB_EMPT1);
    }
    __syncthreads();
    if (wid == 0) TCGEN05_DEALLOC(tmem, 128);

#else  // ---------------- fallback: FFMA2 SGEMM, 128 threads ----------------
    (void)mVhi; (void)mVlo; (void)mThi; (void)mTlo;
    float* As = reinterpret_cast<float*>(gbase);                 // [16][136]
    float* Bs = reinterpret_cast<float*>(gbase + 16 * 136 * 4);  // [16][136]
    int* s_cnt = reinterpret_cast<int*>(gbase + 2 * 16 * 136 * 4);

    const int tx  = tid & 15;   // col group (0..15), 8 cols each
    const int ty2 = tid >> 4;   // row group (0..7), 16 rows each

    u64 acc2[16][4];
    #pragma unroll
    for (int i = 0; i < 16; i++)
        #pragma unroll
        for (int j = 0; j < 4; j++)
            acc2[i][j] = 0ULL;

    for (int k0 = 0; k0 < DD; k0 += 16) {
        #pragma unroll
        for (int l = 0; l < 4; l++) {
            int idx = tid + l * 128;          // 0..511
            int rr  = idx >> 2;               // 0..127
            int c4  = (idx & 3) << 2;         // {0,4,8,12}
            float4 a = *reinterpret_cast<const float4*>(
                V + (size_t)(row0 + rr) * DD + k0 + c4);
            As[(c4 + 0) * 136 + rr] = a.x;
            As[(c4 + 1) * 136 + rr] = a.y;
            As[(c4 + 2) * 136 + rr] = a.z;
            As[(c4 + 3) * 136 + rr] = a.w;
            float4 b = *reinterpret_cast<const float4*>(
                T + (size_t)(col0 + rr) * DD + k0 + c4);
            Bs[(c4 + 0) * 136 + rr] = b.x;
            Bs[(c4 + 1) * 136 + rr] = b.y;
            Bs[(c4 + 2) * 136 + rr] = b.z;
            Bs[(c4 + 3) * 136 + rr] = b.w;
        }
        __syncthreads();

        #pragma unroll
        for (int k = 0; k < 16; k++) {
            float4 b0 = *reinterpret_cast<const float4*>(&Bs[k * 136 + tx * 8]);
            float4 b1 = *reinterpret_cast<const float4*>(&Bs[k * 136 + tx * 8 + 4]);
            u64 bb[4];
            bb[0] = pack2(b0.x, b0.y);
            bb[1] = pack2(b0.z, b0.w);
            bb[2] = pack2(b1.x, b1.y);
            bb[3] = pack2(b1.z, b1.w);
            #pragma unroll
            for (int i = 0; i < 16; i++) {
                float av = As[k * 136 + ty2 * 16 + i];
                u64 aa = pack2(av, av);
                #pragma unroll
                for (int j = 0; j < 4; j++)
                    fma2(acc2[i][j], aa, bb[j]);
            }
        }
        __syncthreads();
    }

    float dr[16], dc[8];
    int cnt_local[16];
    #pragma unroll
    for (int i = 0; i < 16; i++) {
        dr[i] = g_diag[row0 + ty2 * 16 + i];
        cnt_local[i] = 0;
    }
    #pragma unroll
    for (int j = 0; j < 8; j++) dc[j] = g_diag[col0 + tx * 8 + j];

    float vt = 0.f, tv = 0.f;
    #pragma unroll
    for (int i = 0; i < 16; i++) {
        const int r = row0 + ty2 * 16 + i;
        float accrow[8];
        #pragma unroll
        for (int j = 0; j < 4; j++)
            unpack2(acc2[i][j], accrow[2 * j], accrow[2 * j + 1]);
        #pragma unroll
        for (int j = 0; j < 8; j++) {
            const int c = col0 + tx * 8 + j;
            const float s = accrow[j];
            if (r != c) {
                vt += fmaxf(0.f, MARGIN - dr[i] + s);
                tv += fmaxf(0.f, MARGIN - dc[j] + s);
                cnt_local[i] += (s > dr[i]) ? 1 : 0;
            }
        }
    }

    s_cnt[tid] = 0;
    __syncthreads();
    #pragma unroll
    for (int i = 0; i < 16; i++)
        if (cnt_local[i]) atomicAdd(&s_cnt[ty2 * 16 + i], cnt_local[i]);
    __syncthreads();
    {
        int c = s_cnt[tid];
        if (c) atomicAdd(&g_cnt[row0 + tid], c);
    }

    #pragma unroll
    for (int off = 16; off > 0; off >>= 1) {
        vt += __shfl_down_sync(0xFFFFFFFFu, vt, off);
        tv += __shfl_down_sync(0xFFFFFFFFu, tv, off);
    }
    if (lane == 0) {
        atomicAdd(&g_vt_sum, (double)vt);
        atomicAdd(&g_tv_sum, (double)tv);
    }
#endif
}

// ---------------------------------------------------------------------------
// Kernel 4: finalize — recalls, mean rank, normalized losses -> d_out[6]
// ---------------------------------------------------------------------------
__global__ void finalize_kernel(float* __restrict__ out) {
    __shared__ int sA[256], sB[256], sC[256], sD[256];
    const int tid = threadIdx.x;
    int c1 = 0, c5 = 0, c10 = 0, rs = 0;
    for (int i = tid; i < NN; i += 256) {
        int c = g_cnt[i];
        c1  += (c < 1);
        c5  += (c < 5);
        c10 += (c < 10);
        rs  += c;
    }
    sA[tid] = c1; sB[tid] = c5; sC[tid] = c10; sD[tid] = rs;
    __syncthreads();
    for (int s = 128; s > 0; s >>= 1) {
        if (tid < s) {
            sA[tid] += sA[tid + s]; sB[tid] += sB[tid + s];
            sC[tid] += sC[tid + s]; sD[tid] += sD[tid + s];
        }
        __syncthreads();
    }
    if (tid == 0) {
        const double denom = (double)NN * (double)(NN - 1);
        out[0] = (float)(g_vt_sum / denom);
        out[1] = (float)(g_tv_sum / denom);
        out[2] = (float)sA[0] / (float)NN;
        out[3] = (float)sB[0] / (float)NN;
        out[4] = (float)sC[0] / (float)NN;
        out[5] = (float)sD[0] / (float)NN;
    }
}

// ---------------------------------------------------------------------------
typedef CUresult (*EncodeFn)(CUtensorMap*, CUtensorMapDataType, unsigned int,
                             void*, const unsigned long long*,
                             const unsigned long long*, const unsigned int*,
                             const unsigned int*, CUtensorMapInterleave,
                             CUtensorMapSwizzle, CUtensorMapL2promotion,
                             CUtensorMapFloatOOBfill);

static void encode_map(EncodeFn enc, CUtensorMap* m, void* ptr) {
    unsigned long long dims[2]    = {DD, NN};
    unsigned long long strides[1] = {DD * sizeof(__nv_bfloat16)};
    unsigned int box[2]           = {64, 128};
    unsigned int es[2]            = {1, 1};
    enc(m, CU_TENSOR_MAP_DATA_TYPE_BFLOAT16, 2, ptr, dims, strides, box, es,
        CU_TENSOR_MAP_INTERLEAVE_NONE, CU_TENSOR_MAP_SWIZZLE_128B,
        CU_TENSOR_MAP_L2_PROMOTION_L2_128B, CU_TENSOR_MAP_FLOAT_OOB_FILL_NONE);
}

extern "C" void kernel_launch(void* const* d_in, const int* in_sizes, int n_in,
                              void* d_out, int out_size) {
    (void)in_sizes; (void)n_in; (void)out_size;
    const float* V = (const float*)d_in[0];
    const float* T = (const float*)d_in[1];
    float* out = (float*)d_out;

    void *pVhi, *pVlo, *pThi, *pTlo;
    cudaGetSymbolAddress(&pVhi, g_Vhi);
    cudaGetSymbolAddress(&pVlo, g_Vlo);
    cudaGetSymbolAddress(&pThi, g_Thi);
    cudaGetSymbolAddress(&pTlo, g_Tlo);

    void* sym = nullptr;
    cudaDriverEntryPointQueryResult qr;
    cudaGetDriverEntryPointByVersion("cuTensorMapEncodeTiled", &sym, 12000,
                                     cudaEnableDefault, &qr);
    EncodeFn enc = (EncodeFn)sym;

    CUtensorMap mVhi, mVlo, mThi, mTlo;
    encode_map(enc, &mVhi, pVhi);
    encode_map(enc, &mVlo, pVlo);
    encode_map(enc, &mThi, pThi);
    encode_map(enc, &mTlo, pTlo);

    cudaFuncSetAttribute(gemm_tc_kernel,
                         cudaFuncAttributeMaxDynamicSharedMemorySize, SMEM_DYN);

    diag_init_kernel<<<(NN * 32 + 255) / 256, 256>>>(V, T);
    convert_kernel<<<(2 * N4 + 255) / 256, 256>>>(V, T);
    gemm_tc_kernel<<<dim3(32, 32), 128, SMEM_DYN>>>(mVhi, mVlo, mThi, mTlo, V, T);
    finalize_kernel<<<1, 256>>>(out);
}

// round 5
// speedup vs baseline: 1.8836x; 1.0486x over previous
#include <cuda_runtime.h>
#include <cuda_bf16.h>
#include <cuda.h>
#include <stdint.h>

#define NN 4096
#define DD 256
#define MARGIN 0.1f
#define EPS 0.005f

// tcgen05 available only on arch-specific targets (sm_100a / sm_103a)
#if defined(__CUDA_ARCH_FEAT_SM103_ALL) || defined(__CUDA_ARCH_FEAT_SM100_ALL)
#define HAS_TCGEN05 1
#else
#define HAS_TCGEN05 0
#endif

// idesc kind::f16: dtype=F32, atype=btype=BF16, N=256, M=128 (cg1)
#define IDESC 0x08400490u

// tile geometry
#define TM 128
#define TN 256
#define GRID_X (NN / TN)   // 16
#define GRID_Y (NN / TM)   // 32
#define NCTAS (GRID_X * GRID_Y)

// stage layout (bytes): Ahi 16K | Alo 16K | Bhi 32K | Blo 32K
#define ST_ALO   16384
#define ST_BHI   32768
#define ST_BLO   65536
#define ST_BYTES 98304
// control region after 2 stages
#define OFF_TMEMP  (2 * ST_BYTES)            // 196608
#define OFF_MB     (OFF_TMEMP + 16)          // 196624 (4 x 8B)
#define OFF_DC     (OFF_TMEMP + 64)          // 196672 (256 floats)
#define SMEM_DYN   (OFF_DC + 1024 + 1024)    // + s_dc + align slack

typedef unsigned long long u64;

// ---- device-global scratch (no allocations allowed) ----
__device__ double g_vt_sum;
__device__ double g_tv_sum;
__device__ unsigned g_done;
__device__ int    g_cnt[NN];
__device__ float  g_diag[NN];
__device__ __align__(1024) __nv_bfloat16 g_Vhi[NN * DD];
__device__ __align__(1024) __nv_bfloat16 g_Vlo[NN * DD];
__device__ __align__(1024) __nv_bfloat16 g_Thi[NN * DD];
__device__ __align__(1024) __nv_bfloat16 g_Tlo[NN * DD];

// ======================= PTX helpers =======================
__device__ __forceinline__ uint32_t smem_u32(const void* p) {
    uint32_t a;
    asm("{ .reg .u64 t; cvta.to.shared.u64 t, %1; cvt.u32.u64 %0, t; }"
        : "=r"(a) : "l"(p));
    return a;
}

__device__ __forceinline__ u64 pack2(float lo, float hi) {
    u64 r;
    asm("mov.b64 %0, {%1, %2};" : "=l"(r) : "f"(lo), "f"(hi));
    return r;
}
__device__ __forceinline__ void unpack2(u64 v, float& lo, float& hi) {
    asm("mov.b64 {%0, %1}, %2;" : "=f"(lo), "=f"(hi) : "l"(v));
}
__device__ __forceinline__ void fma2(u64& d, u64 a, u64 b) {
    asm("fma.rn.f32x2 %0, %1, %2, %0;" : "+l"(d) : "l"(a), "l"(b));
}

#define MBARRIER_INIT(addr, cnt) \
    asm volatile("mbarrier.init.shared.b64 [%0], %1;" \
        :: "r"((uint32_t)(addr)), "r"((uint32_t)(cnt)) : "memory")

#define MBARRIER_EXPECT_TX(addr, bytes) \
    asm volatile("mbarrier.arrive.expect_tx.shared.b64 _, [%0], %1;" \
        :: "r"((uint32_t)(addr)), "r"((uint32_t)(bytes)) : "memory")

#define MBARRIER_INVAL(addr) \
    asm volatile("mbarrier.inval.shared.b64 [%0];" :: "r"((uint32_t)(addr)) : "memory")

#define MBARRIER_WAIT_PARITY(addr, parity) do {                                   \
    uint32_t _mb = (uint32_t)(addr);                                              \
    uint32_t _ph = (uint32_t)(parity);                                            \
    uint32_t _done;                                                               \
    asm volatile("{\n\t.reg .pred p;\n\t"                                         \
        "mbarrier.try_wait.parity.acquire.cta.shared::cta.b64 p, [%1], %2;\n\t"   \
        "selp.b32 %0, 1, 0, p;\n\t}"                                              \
        : "=r"(_done) : "r"(_mb), "r"(_ph) : "memory");                           \
    if (!_done) {                                                                 \
        asm volatile("{\n\t.reg .pred P1;\n\t"                                    \
            "W_%=:\n\t"                                                           \
            "mbarrier.try_wait.parity.acquire.cta.shared::cta.b64 P1, [%0], %1, 0x989680;\n\t" \
            "@P1 bra.uni D_%=;\n\t"                                               \
            "bra.uni W_%=;\n\t"                                                   \
            "D_%=:\n\t}"                                                          \
            :: "r"(_mb), "r"(_ph) : "memory");                                    \
    }                                                                             \
} while (0)

#if HAS_TCGEN05
#define TCGEN05_ALLOC(res_addr, ncols) \
    asm volatile("tcgen05.alloc.cta_group::1.sync.aligned.shared::cta.b32 [%0], %1;" \
        :: "r"((uint32_t)(res_addr)), "r"((uint32_t)(ncols)) : "memory")
#define TCGEN05_RELINQ() \
    asm volatile("tcgen05.relinquish_alloc_permit.cta_group::1.sync.aligned;")
#define TCGEN05_DEALLOC(tmem, ncols) \
    asm volatile("tcgen05.dealloc.cta_group::1.sync.aligned.b32 %0, %1;" \
        :: "r"(tmem), "r"((uint32_t)(ncols)))
#define TCGEN05_COMMIT(mbar) \
    asm volatile("tcgen05.commit.cta_group::1.mbarrier::arrive::one.shared::cluster.b64 [%0];" \
        :: "r"((uint32_t)(mbar)) : "memory")
#define TCGEN05_FENCE_AFTER() \
    asm volatile("tcgen05.fence::after_thread_sync;" ::: "memory")
#define TCGEN05_FENCE_BEFORE() \
    asm volatile("tcgen05.fence::before_thread_sync;" ::: "memory")
#define TCGEN05_WAIT_LD() \
    asm volatile("tcgen05.wait::ld.sync.aligned;" ::: "memory")

#define TCGEN05_LD_X32(r, addr) \
    asm volatile("tcgen05.ld.sync.aligned.32x32b.x32.b32 " \
        "{%0, %1, %2, %3, %4, %5, %6, %7, %8, %9, %10, %11, %12, %13, %14, %15, " \
        " %16, %17, %18, %19, %20, %21, %22, %23, %24, %25, %26, %27, %28, %29, %30, %31}, [%32];" \
        : "=r"((r)[0]),  "=r"((r)[1]),  "=r"((r)[2]),  "=r"((r)[3]),  \
          "=r"((r)[4]),  "=r"((r)[5]),  "=r"((r)[6]),  "=r"((r)[7]),  \
          "=r"((r)[8]),  "=r"((r)[9]),  "=r"((r)[10]), "=r"((r)[11]), \
          "=r"((r)[12]), "=r"((r)[13]), "=r"((r)[14]), "=r"((r)[15]), \
          "=r"((r)[16]), "=r"((r)[17]), "=r"((r)[18]), "=r"((r)[19]), \
          "=r"((r)[20]), "=r"((r)[21]), "=r"((r)[22]), "=r"((r)[23]), \
          "=r"((r)[24]), "=r"((r)[25]), "=r"((r)[26]), "=r"((r)[27]), \
          "=r"((r)[28]), "=r"((r)[29]), "=r"((r)[30]), "=r"((r)[31]) \
        : "r"(addr))

// SW128 SMEM descriptor: layout=SW128(2), version=1, SBO=64, LBO=1
static __device__ __forceinline__ uint64_t make_desc(uint32_t addr) {
    const uint64_t BASE =
        (uint64_t(2)  << 61) | (uint64_t(1) << 46) |
        (uint64_t(64) << 32) | (uint64_t(1) << 16);
    return BASE | ((uint64_t)(addr >> 4) & 0x3FFF);
}

__device__ __forceinline__ void tma_ld_2d(uint32_t dst, const void* map,
                                          int cx, int cy, uint32_t mbar) {
    asm volatile(
        "cp.async.bulk.tensor.2d.shared::cta.global.tile.mbarrier::complete_tx::bytes "
        "[%0], [%1, {%2, %3}], [%4];"
        :: "r"(dst), "l"(map), "r"(cx), "r"(cy), "r"(mbar) : "memory");
}

__device__ __forceinline__ void mma_f16_ss(uint32_t d, uint64_t da, uint64_t db,
                                           uint32_t en) {
    asm volatile("{\n\t.reg .pred p;\n\tsetp.ne.u32 p, %4, 0;\n\t"
        "tcgen05.mma.cta_group::1.kind::f16 [%0], %1, %2, %3, {%5, %5, %5, %5}, p;\n\t}"
        :: "r"(d), "l"(da), "l"(db), "r"(IDESC), "r"(en), "r"(0u) : "memory");
}
#endif  // HAS_TCGEN05

// ---------------------------------------------------------------------------
// bf16 hi/lo split of a float4 -> two packed uint2
// ---------------------------------------------------------------------------
__device__ __forceinline__ void split4(float4 a, uint2& h, uint2& l) {
    __nv_bfloat162 hxy = __floats2bfloat162_rn(a.x, a.y);
    __nv_bfloat162 hzw = __floats2bfloat162_rn(a.z, a.w);
    float2 fxy = __bfloat1622float2(hxy);
    float2 fzw = __bfloat1622float2(hzw);
    __nv_bfloat162 lxy = __floats2bfloat162_rn(a.x - fxy.x, a.y - fxy.y);
    __nv_bfloat162 lzw = __floats2bfloat162_rn(a.z - fzw.x, a.w - fzw.y);
    h.x = reinterpret_cast<unsigned&>(hxy);
    h.y = reinterpret_cast<unsigned&>(hzw);
    l.x = reinterpret_cast<unsigned&>(lxy);
    l.y = reinterpret_cast<unsigned&>(lzw);
}

// ---------------------------------------------------------------------------
// Kernel 1: fused init — per-row (one warp): bf16 hi/lo split of V and T,
// exact fp32 diag, zero counters/sums.
// ---------------------------------------------------------------------------
__global__ void init_kernel(const float* __restrict__ V,
                            const float* __restrict__ T) {
    const int gtid = blockIdx.x * blockDim.x + threadIdx.x;
    const int row  = gtid >> 5;
    const int lane = gtid & 31;
    if (gtid == 0) { g_vt_sum = 0.0; g_tv_sum = 0.0; g_done = 0u; }
    if (row >= NN) return;

    const float4* v4 = reinterpret_cast<const float4*>(V + (size_t)row * DD);
    const float4* t4 = reinterpret_cast<const float4*>(T + (size_t)row * DD);
    uint2* vh = reinterpret_cast<uint2*>(g_Vhi + (size_t)row * DD);
    uint2* vl = reinterpret_cast<uint2*>(g_Vlo + (size_t)row * DD);
    uint2* th = reinterpret_cast<uint2*>(g_Thi + (size_t)row * DD);
    uint2* tl = reinterpret_cast<uint2*>(g_Tlo + (size_t)row * DD);

    float acc = 0.f;
    #pragma unroll
    for (int p = 0; p < 2; p++) {
        const int idx = lane + p * 32;   // 0..63 float4 per row
        float4 a = v4[idx];
        float4 b = t4[idx];
        acc += a.x * b.x + a.y * b.y + a.z * b.z + a.w * b.w;
        uint2 h, l;
        split4(a, h, l); vh[idx] = h; vl[idx] = l;
        split4(b, h, l); th[idx] = h; tl[idx] = l;
    }
    #pragma unroll
    for (int off = 16; off > 0; off >>= 1)
        acc += __shfl_down_sync(0xFFFFFFFFu, acc, off);
    if (lane == 0) { g_diag[row] = acc; g_cnt[row] = 0; }
}

// ---------------------------------------------------------------------------
// Kernel 2: GEMM + fused ranking epilogue + last-CTA finalize.
//   sm_103a cubin: tcgen05 bf16x3 with TMA pipeline, 128x256 tiles
//   plain cubin:   FFMA2 shared-memory SGEMM fallback (128x128 logic on 256-wide
//                  tile split in two halves)
// Grid (16, 32); 128 threads.
// ---------------------------------------------------------------------------
__global__ __launch_bounds__(128, 1)
void gemm_tc_kernel(const __grid_constant__ CUtensorMap mVhi,
                    const __grid_constant__ CUtensorMap mVlo,
                    const __grid_constant__ CUtensorMap mThi,
                    const __grid_constant__ CUtensorMap mTlo,
                    const float* __restrict__ V,
                    const float* __restrict__ T,
                    float* __restrict__ out) {
    extern __shared__ char smem_raw[];
    const uint32_t raw  = smem_u32(smem_raw);
    const uint32_t base = (raw + 1023) & ~1023u;
    char* gbase = smem_raw + (base - raw);

    const int tid  = threadIdx.x;
    const int lane = tid & 31;
    const int row0 = blockIdx.y * TM;
    const int col0 = blockIdx.x * TN;

#if HAS_TCGEN05
    const int wid = tid >> 5;
    const uint32_t S_TMEMP  = base + OFF_TMEMP;
    const uint32_t MB_FULL0 = base + OFF_MB;
    const uint32_t MB_FULL1 = base + OFF_MB + 8;
    const uint32_t MB_EMPT0 = base + OFF_MB + 16;
    const uint32_t MB_EMPT1 = base + OFF_MB + 24;
    float* s_dc = reinterpret_cast<float*>(gbase + OFF_DC);

    if (wid == 0) {
        TCGEN05_ALLOC(S_TMEMP, 256);
        TCGEN05_RELINQ();
    }
    if (tid == 0) {
        MBARRIER_INIT(MB_FULL0, 1);
        MBARRIER_INIT(MB_FULL1, 1);
        MBARRIER_INIT(MB_EMPT0, 1);
        MBARRIER_INIT(MB_EMPT1, 1);
    }
    __syncthreads();
    uint32_t tmem;
    asm volatile("ld.shared.b32 %0, [%1];" : "=r"(tmem) : "r"(S_TMEMP));

    if (tid == 0) {
        #pragma unroll
        for (int c = 0; c < 2; c++) {
            uint32_t st = base + c * ST_BYTES;
            uint32_t mb = c ? MB_FULL1 : MB_FULL0;
            MBARRIER_EXPECT_TX(mb, ST_BYTES);
            tma_ld_2d(st +      0, &mVhi, c * 64, row0, mb);
            tma_ld_2d(st + ST_ALO, &mVlo, c * 64, row0, mb);
            tma_ld_2d(st + ST_BHI, &mThi, c * 64, col0, mb);
            tma_ld_2d(st + ST_BLO, &mTlo, c * 64, col0, mb);
        }
        for (int c = 0; c < 4; c++) {
            const int s = c & 1;
            const uint32_t full  = s ? MB_FULL1 : MB_FULL0;
            const uint32_t empty = s ? MB_EMPT1 : MB_EMPT0;
            const uint32_t st    = base + s * ST_BYTES;
            MBARRIER_WAIT_PARITY(full, c >> 1);
            const uint64_t dAhi = make_desc(st);
            const uint64_t dAlo = make_desc(st + ST_ALO);
            const uint64_t dBhi = make_desc(st + ST_BHI);
            const uint64_t dBlo = make_desc(st + ST_BLO);
            #pragma unroll
            for (int ks = 0; ks < 4; ks++)
                mma_f16_ss(tmem, dAhi + ks * 2, dBhi + ks * 2,
                           (c == 0 && ks == 0) ? 0u : 1u);
            #pragma unroll
            for (int ks = 0; ks < 4; ks++)
                mma_f16_ss(tmem, dAhi + ks * 2, dBlo + ks * 2, 1u);
            #pragma unroll
            for (int ks = 0; ks < 4; ks++)
                mma_f16_ss(tmem, dAlo + ks * 2, dBhi + ks * 2, 1u);
            TCGEN05_COMMIT(empty);
            if (c < 2) {
                MBARRIER_WAIT_PARITY(empty, 0);
                const int c2 = c + 2;
                MBARRIER_EXPECT_TX(full, ST_BYTES);
                tma_ld_2d(st +      0, &mVhi, c2 * 64, row0, full);
                tma_ld_2d(st + ST_ALO, &mVlo, c2 * 64, row0, full);
                tma_ld_2d(st + ST_BHI, &mThi, c2 * 64, col0, full);
                tma_ld_2d(st + ST_BLO, &mTlo, c2 * 64, col0, full);
            }
        }
    }

    s_dc[tid]       = g_diag[col0 + tid];
    s_dc[tid + 128] = g_diag[col0 + tid + 128];

    MBARRIER_WAIT_PARITY(MB_EMPT0, 1);
    MBARRIER_WAIT_PARITY(MB_EMPT1, 1);
    TCGEN05_FENCE_AFTER();
    __syncthreads();

    const int r = row0 + tid;
    const float dr = g_diag[r];
    float vt = 0.f, tv = 0.f;
    int cnt = 0;

    #pragma unroll 1
    for (int g = 0; g < 8; g++) {
        uint32_t dreg[32];
        TCGEN05_LD_X32(dreg, tmem + g * 32);
        TCGEN05_WAIT_LD();
        #pragma unroll
        for (int j = 0; j < 32; j++) {
            const int cc = g * 32 + j;
            const int c  = col0 + cc;
            const float sv = __uint_as_float(dreg[j]);
            if (c != r) {
                vt += fmaxf(0.f, MARGIN - dr + sv);
                tv += fmaxf(0.f, MARGIN - s_dc[cc] + sv);
                const float diff = sv - dr;
                if (fabsf(diff) < EPS) {
                    const float4* a4 = reinterpret_cast<const float4*>(V + (size_t)r * DD);
                    const float4* b4 = reinterpret_cast<const float4*>(T + (size_t)c * DD);
                    float ex = 0.f;
                    #pragma unroll 8
                    for (int k = 0; k < DD / 4; k++) {
                        float4 x = a4[k], y = b4[k];
                        ex += x.x * y.x + x.y * y.y + x.z * y.z + x.w * y.w;
                    }
                    cnt += (ex > dr) ? 1 : 0;
                } else {
                    cnt += (diff > 0.f) ? 1 : 0;
                }
            }
        }
    }
    TCGEN05_FENCE_BEFORE();

    atomicAdd(&g_cnt[r], cnt);
    #pragma unroll
    for (int off = 16; off > 0; off >>= 1) {
        vt += __shfl_down_sync(0xFFFFFFFFu, vt, off);
        tv += __shfl_down_sync(0xFFFFFFFFu, tv, off);
    }
    if (lane == 0) {
        atomicAdd(&g_vt_sum, (double)vt);
        atomicAdd(&g_tv_sum, (double)tv);
    }

    __syncthreads();
    if (tid == 0) {
        MBARRIER_INVAL(MB_FULL0); MBARRIER_INVAL(MB_FULL1);
        MBARRIER_INVAL(MB_EMPT0); MBARRIER_INVAL(MB_EMPT1);
    }
    __syncthreads();
    if (wid == 0) TCGEN05_DEALLOC(tmem, 256);

#else  // ---------------- fallback: FFMA2 SGEMM over the 128x256 tile -------
    (void)mVhi; (void)mVlo; (void)mThi; (void)mTlo;
    float* As = reinterpret_cast<float*>(gbase);                 // [16][136]
    float* Bs = reinterpret_cast<float*>(gbase + 16 * 136 * 4);  // [16][136]
    int* s_cnt = reinterpret_cast<int*>(gbase + 2 * 16 * 136 * 4);

    const int tx  = tid & 15;
    const int ty2 = tid >> 4;

    float vt = 0.f, tv = 0.f;
    int cnt_row[16];
    #pragma unroll
    for (int i = 0; i < 16; i++) cnt_row[i] = 0;

    for (int half = 0; half < 2; half++) {
        const int colh = col0 + half * 128;
        u64 acc2[16][4];
        #pragma unroll
        for (int i = 0; i < 16; i++)
            #pragma unroll
            for (int j = 0; j < 4; j++)
                acc2[i][j] = 0ULL;

        for (int k0 = 0; k0 < DD; k0 += 16) {
            #pragma unroll
            for (int l = 0; l < 4; l++) {
                int idx = tid + l * 128;
                int rr  = idx >> 2;
                int c4  = (idx & 3) << 2;
                float4 a = *reinterpret_cast<const float4*>(
                    V + (size_t)(row0 + rr) * DD + k0 + c4);
                As[(c4 + 0) * 136 + rr] = a.x;
                As[(c4 + 1) * 136 + rr] = a.y;
                As[(c4 + 2) * 136 + rr] = a.z;
                As[(c4 + 3) * 136 + rr] = a.w;
                float4 b = *reinterpret_cast<const float4*>(
                    T + (size_t)(colh + rr) * DD + k0 + c4);
                Bs[(c4 + 0) * 136 + rr] = b.x;
                Bs[(c4 + 1) * 136 + rr] = b.y;
                Bs[(c4 + 2) * 136 + rr] = b.z;
                Bs[(c4 + 3) * 136 + rr] = b.w;
            }
            __syncthreads();
            #pragma unroll
            for (int k = 0; k < 16; k++) {
                float4 b0 = *reinterpret_cast<const float4*>(&Bs[k * 136 + tx * 8]);
                float4 b1 = *reinterpret_cast<const float4*>(&Bs[k * 136 + tx * 8 + 4]);
                u64 bb[4];
                bb[0] = pack2(b0.x, b0.y);
                bb[1] = pack2(b0.z, b0.w);
                bb[2] = pack2(b1.x, b1.y);
                bb[3] = pack2(b1.z, b1.w);
                #pragma unroll
                for (int i = 0; i < 16; i++) {
                    float av = As[k * 136 + ty2 * 16 + i];
                    u64 aa = pack2(av, av);
                    #pragma unroll
                    for (int j = 0; j < 4; j++)
                        fma2(acc2[i][j], aa, bb[j]);
                }
            }
            __syncthreads();
        }

        #pragma unroll
        for (int i = 0; i < 16; i++) {
            const int rr = row0 + ty2 * 16 + i;
            const float dri = g_diag[rr];
            float accrow[8];
            #pragma unroll
            for (int j = 0; j < 4; j++)
                unpack2(acc2[i][j], accrow[2 * j], accrow[2 * j + 1]);
            #pragma unroll
            for (int j = 0; j < 8; j++) {
                const int c = colh + tx * 8 + j;
                const float s = accrow[j];
                if (rr != c) {
                    vt += fmaxf(0.f, MARGIN - dri + s);
                    tv += fmaxf(0.f, MARGIN - g_diag[c] + s);
                    cnt_row[i] += (s > dri) ? 1 : 0;
                }
            }
        }
    }

    s_cnt[tid] = 0;
    __syncthreads();
    #pragma unroll
    for (int i = 0; i < 16; i++)
        if (cnt_row[i]) atomicAdd(&s_cnt[ty2 * 16 + i], cnt_row[i]);
    __syncthreads();
    {
        int c = s_cnt[tid];
        if (c) atomicAdd(&g_cnt[row0 + tid], c);
    }
    #pragma unroll
    for (int off = 16; off > 0; off >>= 1) {
        vt += __shfl_down_sync(0xFFFFFFFFu, vt, off);
        tv += __shfl_down_sync(0xFFFFFFFFu, tv, off);
    }
    if (lane == 0) {
        atomicAdd(&g_vt_sum, (double)vt);
        atomicAdd(&g_tv_sum, (double)tv);
    }
#endif

    // ---- last-CTA finalize ----
    __shared__ unsigned s_last;
    __shared__ int rA[128], rB[128], rC[128], rD[128];
    __threadfence();
    __syncthreads();
    if (tid == 0) s_last = (atomicAdd(&g_done, 1u) == (unsigned)(NCTAS - 1));
    __syncthreads();
    if (!s_last) return;

    int c1 = 0, c5 = 0, c10 = 0, rs = 0;
    for (int i = tid; i < NN; i += 128) {
        int c = g_cnt[i];
        c1  += (c < 1);
        c5  += (c < 5);
        c10 += (c < 10);
        rs  += c;
    }
    rA[tid] = c1; rB[tid] = c5; rC[tid] = c10; rD[tid] = rs;
    __syncthreads();
    for (int s = 64; s > 0; s >>= 1) {
        if (tid < s) {
            rA[tid] += rA[tid + s]; rB[tid] += rB[tid + s];
            rC[tid] += rC[tid + s]; rD[tid] += rD[tid + s];
        }
        __syncthreads();
    }
    if (tid == 0) {
        const double denom = (double)NN * (double)(NN - 1);
        out[0] = (float)(g_vt_sum / denom);
        out[1] = (float)(g_tv_sum / denom);
        out[2] = (float)rA[0] / (float)NN;
        out[3] = (float)rB[0] / (float)NN;
        out[4] = (float)rC[0] / (float)NN;
        out[5] = (float)rD[0] / (float)NN;
    }
}

// ---------------------------------------------------------------------------
typedef CUresult (*EncodeFn)(CUtensorMap*, CUtensorMapDataType, unsigned int,
                             void*, const unsigned long long*,
                             const unsigned long long*, const unsigned int*,
                             const unsigned int*, CUtensorMapInterleave,
                             CUtensorMapSwizzle, CUtensorMapL2promotion,
                             CUtensorMapFloatOOBfill);

static void encode_map(EncodeFn enc, CUtensorMap* m, void* ptr, unsigned rows) {
    unsigned long long dims[2]    = {DD, NN};
    unsigned long long strides[1] = {DD * sizeof(__nv_bfloat16)};
    unsigned int box[2]           = {64, rows};
    unsigned int es[2]            = {1, 1};
    enc(m, CU_TENSOR_MAP_DATA_TYPE_BFLOAT16, 2, ptr, dims, strides, box, es,
        CU_TENSOR_MAP_INTERLEAVE_NONE, CU_TENSOR_MAP_SWIZZLE_128B,
        CU_TENSOR_MAP_L2_PROMOTION_L2_128B, CU_TENSOR_MAP_FLOAT_OOB_FILL_NONE);
}

extern "C" void kernel_launch(void* const* d_in, const int* in_sizes, int n_in,
                              void* d_out, int out_size) {
    (void)in_sizes; (void)n_in; (void)out_size;
    const float* V = (const float*)d_in[0];
    const float* T = (const float*)d_in[1];
    float* out = (float*)d_out;

    void *pVhi, *pVlo, *pThi, *pTlo;
    cudaGetSymbolAddress(&pVhi, g_Vhi);
    cudaGetSymbolAddress(&pVlo, g_Vlo);
    cudaGetSymbolAddress(&pThi, g_Thi);
    cudaGetSymbolAddress(&pTlo, g_Tlo);

    void* sym = nullptr;
    cudaDriverEntryPointQueryResult qr;
    cudaGetDriverEntryPointByVersion("cuTensorMapEncodeTiled", &sym, 12000,
                                     cudaEnableDefault, &qr);
    EncodeFn enc = (EncodeFn)sym;

    CUtensorMap mVhi, mVlo, mThi, mTlo;
    encode_map(enc, &mVhi, pVhi, TM);   // A tiles: 128 rows
    encode_map(enc, &mVlo, pVlo, TM);
    encode_map(enc, &mThi, pThi, TN);   // B tiles: 256 rows
    encode_map(enc, &mTlo, pTlo, TN);

    cudaFuncSetAttribute(gemm_tc_kernel,
                         cudaFuncAttributeMaxDynamicSharedMemorySize, SMEM_DYN);

    init_kernel<<<NN * 32 / 256, 256>>>(V, T);
    gemm_tc_kernel<<<dim3(GRID_X, GRID_Y), 128, SMEM_DYN>>>(
        mVhi, mVlo, mThi, mTlo, V, T, out);
}

// round 6
// speedup vs baseline: 2.0441x; 1.0852x over previous
#include <cuda_runtime.h>
#include <cuda_bf16.h>
#include <cuda.h>
#include <stdint.h>

#define NN 4096
#define DD 256
#define MARGIN 0.1f
#define EPS 0.005f

#if defined(__CUDA_ARCH_FEAT_SM103_ALL) || defined(__CUDA_ARCH_FEAT_SM100_ALL)
#define HAS_TCGEN05 1
#else
#define HAS_TCGEN05 0
#endif

// idesc kind::f16: dtype=F32, atype=btype=BF16, N=256, M=128 (cg1)
#define IDESC 0x08400490u

// tile geometry
#define TM 128
#define TN 256
#define TILES_X (NN / TN)            // 16
#define TILES_Y (NN / TM)            // 32
#define NTILES  (TILES_X * TILES_Y)  // 512
#define NCTA    148
#define NTHREADS 160                 // 4 consumer warps + 1 producer warp

// stage layout (bytes): Ahi 16K | Alo 16K | Bhi 32K | Blo 32K
#define ST_ALO   16384
#define ST_BHI   32768
#define ST_BLO   65536
#define ST_BYTES 98304
#define OFF_TMEMP  (2 * ST_BYTES)         // 196608
#define OFF_MB     (OFF_TMEMP + 16)
#define SMEM_DYN   (OFF_TMEMP + 128 + 1024)

typedef unsigned long long u64;

// ---- device-global scratch ----
__device__ double g_vt_sum;
__device__ double g_tv_sum;
__device__ unsigned g_done;
__device__ int    g_cnt[NN];
__device__ float  g_diag[NN];
__device__ __align__(1024) __nv_bfloat16 g_Vhi[NN * DD];
__device__ __align__(1024) __nv_bfloat16 g_Vlo[NN * DD];
__device__ __align__(1024) __nv_bfloat16 g_Thi[NN * DD];
__device__ __align__(1024) __nv_bfloat16 g_Tlo[NN * DD];

// ======================= PTX helpers =======================
__device__ __forceinline__ uint32_t smem_u32(const void* p) {
    uint32_t a;
    asm("{ .reg .u64 t; cvta.to.shared.u64 t, %1; cvt.u32.u64 %0, t; }"
        : "=r"(a) : "l"(p));
    return a;
}

#define MBARRIER_INIT(addr, cnt) \
    asm volatile("mbarrier.init.shared.b64 [%0], %1;" \
        :: "r"((uint32_t)(addr)), "r"((uint32_t)(cnt)) : "memory")

#define MBARRIER_EXPECT_TX(addr, bytes) \
    asm volatile("mbarrier.arrive.expect_tx.shared.b64 _, [%0], %1;" \
        :: "r"((uint32_t)(addr)), "r"((uint32_t)(bytes)) : "memory")

#define MBARRIER_ARRIVE(addr) \
    asm volatile("mbarrier.arrive.shared.b64 _, [%0];" \
        :: "r"((uint32_t)(addr)) : "memory")

#define MBARRIER_WAIT_PARITY(addr, parity) do {                                   \
    uint32_t _mb = (uint32_t)(addr);                                              \
    uint32_t _ph = (uint32_t)(parity);                                            \
    uint32_t _done;                                                               \
    asm volatile("{\n\t.reg .pred p;\n\t"                                         \
        "mbarrier.try_wait.parity.acquire.cta.shared::cta.b64 p, [%1], %2;\n\t"   \
        "selp.b32 %0, 1, 0, p;\n\t}"                                              \
        : "=r"(_done) : "r"(_mb), "r"(_ph) : "memory");                           \
    if (!_done) {                                                                 \
        asm volatile("{\n\t.reg .pred P1;\n\t"                                    \
            "W_%=:\n\t"                                                           \
            "mbarrier.try_wait.parity.acquire.cta.shared::cta.b64 P1, [%0], %1, 0x989680;\n\t" \
            "@P1 bra.uni D_%=;\n\t"                                               \
            "bra.uni W_%=;\n\t"                                                   \
            "D_%=:\n\t}"                                                          \
            :: "r"(_mb), "r"(_ph) : "memory");                                    \
    }                                                                             \
} while (0)

#if HAS_TCGEN05
#define TCGEN05_ALLOC(res_addr, ncols) \
    asm volatile("tcgen05.alloc.cta_group::1.sync.aligned.shared::cta.b32 [%0], %1;" \
        :: "r"((uint32_t)(res_addr)), "r"((uint32_t)(ncols)) : "memory")
#define TCGEN05_RELINQ() \
    asm volatile("tcgen05.relinquish_alloc_permit.cta_group::1.sync.aligned;")
#define TCGEN05_DEALLOC(tmem, ncols) \
    asm volatile("tcgen05.dealloc.cta_group::1.sync.aligned.b32 %0, %1;" \
        :: "r"(tmem), "r"((uint32_t)(ncols)))
#define TCGEN05_COMMIT(mbar) \
    asm volatile("tcgen05.commit.cta_group::1.mbarrier::arrive::one.shared::cluster.b64 [%0];" \
        :: "r"((uint32_t)(mbar)) : "memory")
#define TCGEN05_FENCE_AFTER() \
    asm volatile("tcgen05.fence::after_thread_sync;" ::: "memory")
#define TCGEN05_FENCE_BEFORE() \
    asm volatile("tcgen05.fence::before_thread_sync;" ::: "memory")
#define TCGEN05_WAIT_LD() \
    asm volatile("tcgen05.wait::ld.sync.aligned;" ::: "memory")

#define TCGEN05_LD_X32(r, addr) \
    asm volatile("tcgen05.ld.sync.aligned.32x32b.x32.b32 " \
        "{%0, %1, %2, %3, %4, %5, %6, %7, %8, %9, %10, %11, %12, %13, %14, %15, " \
        " %16, %17, %18, %19, %20, %21, %22, %23, %24, %25, %26, %27, %28, %29, %30, %31}, [%32];" \
        : "=r"((r)[0]),  "=r"((r)[1]),  "=r"((r)[2]),  "=r"((r)[3]),  \
          "=r"((r)[4]),  "=r"((r)[5]),  "=r"((r)[6]),  "=r"((r)[7]),  \
          "=r"((r)[8]),  "=r"((r)[9]),  "=r"((r)[10]), "=r"((r)[11]), \
          "=r"((r)[12]), "=r"((r)[13]), "=r"((r)[14]), "=r"((r)[15]), \
          "=r"((r)[16]), "=r"((r)[17]), "=r"((r)[18]), "=r"((r)[19]), \
          "=r"((r)[20]), "=r"((r)[21]), "=r"((r)[22]), "=r"((r)[23]), \
          "=r"((r)[24]), "=r"((r)[25]), "=r"((r)[26]), "=r"((r)[27]), \
          "=r"((r)[28]), "=r"((r)[29]), "=r"((r)[30]), "=r"((r)[31]) \
        : "r"(addr))

// SW128 SMEM descriptor: layout=SW128(2), version=1, SBO=64, LBO=1
static __device__ __forceinline__ uint64_t make_desc(uint32_t addr) {
    const uint64_t BASE =
        (uint64_t(2)  << 61) | (uint64_t(1) << 46) |
        (uint64_t(64) << 32) | (uint64_t(1) << 16);
    return BASE | ((uint64_t)(addr >> 4) & 0x3FFF);
}

__device__ __forceinline__ void tma_ld_2d(uint32_t dst, const void* map,
                                          int cx, int cy, uint32_t mbar) {
    asm volatile(
        "cp.async.bulk.tensor.2d.shared::cta.global.tile.mbarrier::complete_tx::bytes "
        "[%0], [%1, {%2, %3}], [%4];"
        :: "r"(dst), "l"(map), "r"(cx), "r"(cy), "r"(mbar) : "memory");
}

__device__ __forceinline__ void mma_f16_ss(uint32_t d, uint64_t da, uint64_t db,
                                           uint32_t en) {
    asm volatile("{\n\t.reg .pred p;\n\tsetp.ne.u32 p, %4, 0;\n\t"
        "tcgen05.mma.cta_group::1.kind::f16 [%0], %1, %2, %3, {%5, %5, %5, %5}, p;\n\t}"
        :: "r"(d), "l"(da), "l"(db), "r"(IDESC), "r"(en), "r"(0u) : "memory");
}
#endif  // HAS_TCGEN05

// ---------------------------------------------------------------------------
__device__ __forceinline__ void split4(float4 a, uint2& h, uint2& l) {
    __nv_bfloat162 hxy = __floats2bfloat162_rn(a.x, a.y);
    __nv_bfloat162 hzw = __floats2bfloat162_rn(a.z, a.w);
    float2 fxy = __bfloat1622float2(hxy);
    float2 fzw = __bfloat1622float2(hzw);
    __nv_bfloat162 lxy = __floats2bfloat162_rn(a.x - fxy.x, a.y - fxy.y);
    __nv_bfloat162 lzw = __floats2bfloat162_rn(a.z - fzw.x, a.w - fzw.y);
    h.x = reinterpret_cast<unsigned&>(hxy);
    h.y = reinterpret_cast<unsigned&>(hzw);
    l.x = reinterpret_cast<unsigned&>(lxy);
    l.y = reinterpret_cast<unsigned&>(lzw);
}

// ---------------------------------------------------------------------------
// Kernel 1: fused init — bf16 hi/lo split, exact fp32 diag, zero counters.
// ---------------------------------------------------------------------------
__global__ void init_kernel(const float* __restrict__ V,
                            const float* __restrict__ T) {
    const int gtid = blockIdx.x * blockDim.x + threadIdx.x;
    const int row  = gtid >> 5;
    const int lane = gtid & 31;
    if (gtid == 0) { g_vt_sum = 0.0; g_tv_sum = 0.0; g_done = 0u; }
    if (row >= NN) return;

    const float4* v4 = reinterpret_cast<const float4*>(V + (size_t)row * DD);
    const float4* t4 = reinterpret_cast<const float4*>(T + (size_t)row * DD);
    uint2* vh = reinterpret_cast<uint2*>(g_Vhi + (size_t)row * DD);
    uint2* vl = reinterpret_cast<uint2*>(g_Vlo + (size_t)row * DD);
    uint2* th = reinterpret_cast<uint2*>(g_Thi + (size_t)row * DD);
    uint2* tl = reinterpret_cast<uint2*>(g_Tlo + (size_t)row * DD);

    float acc = 0.f;
    #pragma unroll
    for (int p = 0; p < 2; p++) {
        const int idx = lane + p * 32;
        float4 a = v4[idx];
        float4 b = t4[idx];
        acc += a.x * b.x + a.y * b.y + a.z * b.z + a.w * b.w;
        uint2 h, l;
        split4(a, h, l); vh[idx] = h; vl[idx] = l;
        split4(b, h, l); th[idx] = h; tl[idx] = l;
    }
    #pragma unroll
    for (int off = 16; off > 0; off >>= 1)
        acc += __shfl_down_sync(0xFFFFFFFFu, acc, off);
    if (lane == 0) { g_diag[row] = acc; g_cnt[row] = 0; }
}

// ---------------------------------------------------------------------------
// Kernel 2: persistent warp-specialized tcgen05 GEMM + ranking epilogue +
// last-CTA finalize. 148 CTAs x 160 threads.
//   warps 0-3 : epilogue consumers (row = tid)
//   warp 4    : producer (thread 128 issues TMA + MMA)
// TMEM: two 256-col fp32 accumulator buffers, alternating per tile.
// ---------------------------------------------------------------------------
__global__ __launch_bounds__(NTHREADS, 1)
void gemm_tc_kernel(const __grid_constant__ CUtensorMap mVhi,
                    const __grid_constant__ CUtensorMap mVlo,
                    const __grid_constant__ CUtensorMap mThi,
                    const __grid_constant__ CUtensorMap mTlo,
                    const float* __restrict__ V,
                    const float* __restrict__ T,
                    float* __restrict__ out) {
    extern __shared__ char smem_raw[];
    const uint32_t raw  = smem_u32(smem_raw);
    const uint32_t base = (raw + 1023) & ~1023u;

    const int tid  = threadIdx.x;
    const int lane = tid & 31;
    const int cta  = blockIdx.x;
    const int ntiles = (NTILES - cta + NCTA - 1) / NCTA;  // tiles for this CTA

    float vt = 0.f, tv = 0.f;   // accumulated across all tiles

#if HAS_TCGEN05
    const int wid = tid >> 5;
    const uint32_t S_TMEMP = base + OFF_TMEMP;
    const uint32_t MB_FULL = base + OFF_MB;        // +0, +8
    const uint32_t MB_EMPT = base + OFF_MB + 16;   // +16, +24
    const uint32_t MB_RES  = base + OFF_MB + 32;   // +32, +40
    const uint32_t MB_EPI  = base + OFF_MB + 48;   // +48, +56

    if (wid == 4) {
        TCGEN05_ALLOC(S_TMEMP, 512);
        TCGEN05_RELINQ();
    }
    if (tid == 0) {
        MBARRIER_INIT(MB_FULL + 0, 1);
        MBARRIER_INIT(MB_FULL + 8, 1);
        MBARRIER_INIT(MB_EMPT + 0, 1);
        MBARRIER_INIT(MB_EMPT + 8, 1);
        MBARRIER_INIT(MB_RES  + 0, 1);
        MBARRIER_INIT(MB_RES  + 8, 1);
        MBARRIER_INIT(MB_EPI  + 0, 4);
        MBARRIER_INIT(MB_EPI  + 8, 4);
    }
    __syncthreads();
    uint32_t tmem;
    asm volatile("ld.shared.b32 %0, [%1];" : "=r"(tmem) : "r"(S_TMEMP));

    if (tid == 128) {
        // ---------------- producer ----------------
        const int nchunks = ntiles * 4;

        // TMA issue for local chunk kk
        auto issue_tma = [&](int kk) {
            const int lt    = kk >> 2;
            const int chunk = kk & 3;
            const int s     = kk & 1;
            const int tile  = cta + lt * NCTA;
            const int row0  = (tile >> 4) * TM;
            const int col0  = (tile & 15) * TN;
            const uint32_t st = base + s * ST_BYTES;
            const uint32_t fb = MB_FULL + s * 8;
            MBARRIER_EXPECT_TX(fb, ST_BYTES);
            tma_ld_2d(st +      0, &mVhi, chunk * 64, row0, fb);
            tma_ld_2d(st + ST_ALO, &mVlo, chunk * 64, row0, fb);
            tma_ld_2d(st + ST_BHI, &mThi, chunk * 64, col0, fb);
            tma_ld_2d(st + ST_BLO, &mTlo, chunk * 64, col0, fb);
        };

        issue_tma(0);
        if (nchunks > 1) issue_tma(1);

        for (int kk = 0; kk < nchunks; kk++) {
            const int s     = kk & 1;
            const int lt    = kk >> 2;
            const int chunk = kk & 3;
            const int buf   = lt & 1;
            const uint32_t st = base + s * ST_BYTES;
            const uint32_t dbuf = tmem + buf * 256;

            MBARRIER_WAIT_PARITY(MB_FULL + s * 8, (kk >> 1) & 1);
            if (chunk == 0 && lt >= 2)
                MBARRIER_WAIT_PARITY(MB_EPI + buf * 8, ((lt - 2) >> 1) & 1);

            const uint64_t dAhi = make_desc(st);
            const uint64_t dAlo = make_desc(st + ST_ALO);
            const uint64_t dBhi = make_desc(st + ST_BHI);
            const uint64_t dBlo = make_desc(st + ST_BLO);
            #pragma unroll
            for (int ks = 0; ks < 4; ks++)
                mma_f16_ss(dbuf, dAhi + ks * 2, dBhi + ks * 2,
                           (chunk == 0 && ks == 0) ? 0u : 1u);
            #pragma unroll
            for (int ks = 0; ks < 4; ks++)
                mma_f16_ss(dbuf, dAhi + ks * 2, dBlo + ks * 2, 1u);
            #pragma unroll
            for (int ks = 0; ks < 4; ks++)
                mma_f16_ss(dbuf, dAlo + ks * 2, dBhi + ks * 2, 1u);

            TCGEN05_COMMIT(MB_EMPT + s * 8);
            if (chunk == 3) TCGEN05_COMMIT(MB_RES + buf * 8);

            if (kk + 2 < nchunks) {
                MBARRIER_WAIT_PARITY(MB_EMPT + s * 8, (kk >> 1) & 1);
                issue_tma(kk + 2);
            }
        }
    } else if (tid < 128) {
        // ---------------- consumers ----------------
        int done_r[4];   // rows already counted? not needed; per-tile atomics
        (void)done_r;
        for (int lt = 0; lt < ntiles; lt++) {
            const int buf  = lt & 1;
            const int tile = cta + lt * NCTA;
            const int row0 = (tile >> 4) * TM;
            const int col0 = (tile & 15) * TN;
            const int r    = row0 + tid;
            const float dr = g_diag[r];
            const uint32_t dbuf = tmem + buf * 256;
            int cnt = 0;

            MBARRIER_WAIT_PARITY(MB_RES + buf * 8, (lt >> 1) & 1);
            TCGEN05_FENCE_AFTER();

            #pragma unroll 1
            for (int g = 0; g < 8; g++) {
                uint32_t dreg[32];
                TCGEN05_LD_X32(dreg, dbuf + g * 32);
                TCGEN05_WAIT_LD();
                #pragma unroll
                for (int j = 0; j < 32; j++) {
                    const int cc = g * 32 + j;
                    const int c  = col0 + cc;
                    const float sv = __uint_as_float(dreg[j]);
                    if (c != r) {
                        const float dc = __ldg(g_diag + c);
                        vt += fmaxf(0.f, MARGIN - dr + sv);
                        tv += fmaxf(0.f, MARGIN - dc + sv);
                        const float diff = sv - dr;
                        if (fabsf(diff) < EPS) {
                            const float4* a4 = reinterpret_cast<const float4*>(V + (size_t)r * DD);
                            const float4* b4 = reinterpret_cast<const float4*>(T + (size_t)c * DD);
                            float ex = 0.f;
                            #pragma unroll 8
                            for (int k = 0; k < DD / 4; k++) {
                                float4 x = a4[k], y = b4[k];
                                ex += x.x * y.x + x.y * y.y + x.z * y.z + x.w * y.w;
                            }
                            cnt += (ex > dr) ? 1 : 0;
                        } else {
                            cnt += (diff > 0.f) ? 1 : 0;
                        }
                    }
                }
            }
            TCGEN05_FENCE_BEFORE();
            if (lane == 0) MBARRIER_ARRIVE(MB_EPI + buf * 8);
            atomicAdd(&g_cnt[r], cnt);
        }
    }

    __syncthreads();           // everyone done with TMEM
    if (wid == 4) TCGEN05_DEALLOC(tmem, 512);

#else  // ---------------- fallback: plain fp32 (never selected on GB300) ----
    (void)mVhi; (void)mVlo; (void)mThi; (void)mTlo;
    for (int lt = 0; lt < ntiles; lt++) {
        const int tile = cta + lt * NCTA;
        const int row0 = (tile >> 4) * TM;
        const int col0 = (tile & 15) * TN;
        if (tid < 128) {
            const int r = row0 + tid;
            const float dr = g_diag[r];
            const float4* a4 = reinterpret_cast<const float4*>(V + (size_t)r * DD);
            int cnt = 0;
            for (int cc = 0; cc < TN; cc++) {
                const int c = col0 + cc;
                if (c == r) continue;
                const float4* b4 = reinterpret_cast<const float4*>(T + (size_t)c * DD);
                float s = 0.f;
                #pragma unroll 8
                for (int k = 0; k < DD / 4; k++) {
                    float4 x = a4[k], y = b4[k];
                    s += x.x * y.x + x.y * y.y + x.z * y.z + x.w * y.w;
                }
                vt += fmaxf(0.f, MARGIN - dr + s);
                tv += fmaxf(0.f, MARGIN - g_diag[c] + s);
                cnt += (s > dr) ? 1 : 0;
            }
            atomicAdd(&g_cnt[r], cnt);
        }
    }
    __syncthreads();
#endif

    // loss reduction: one double atomic per warp
    #pragma unroll
    for (int off = 16; off > 0; off >>= 1) {
        vt += __shfl_down_sync(0xFFFFFFFFu, vt, off);
        tv += __shfl_down_sync(0xFFFFFFFFu, tv, off);
    }
    if (lane == 0 && tid < 128) {
        atomicAdd(&g_vt_sum, (double)vt);
        atomicAdd(&g_tv_sum, (double)tv);
    }

    // ---- last-CTA finalize ----
    __shared__ unsigned s_last;
    __shared__ int rA[NTHREADS], rB[NTHREADS], rC[NTHREADS], rD[NTHREADS];
    __threadfence();
    __syncthreads();
    if (tid == 0) s_last = (atomicAdd(&g_done, 1u) == (unsigned)(NCTA - 1));
    __syncthreads();
    if (!s_last) return;

    int c1 = 0, c5 = 0, c10 = 0, rs = 0;
    for (int i = tid; i < NN; i += NTHREADS) {
        int c = g_cnt[i];
        c1  += (c < 1);
        c5  += (c < 5);
        c10 += (c < 10);
        rs  += c;
    }
    rA[tid] = c1; rB[tid] = c5; rC[tid] = c10; rD[tid] = rs;
    __syncthreads();
    if (tid < 32) {
        rA[tid] += rA[tid + 128]; rB[tid] += rB[tid + 128];
        rC[tid] += rC[tid + 128]; rD[tid] += rD[tid + 128];
    }
    __syncthreads();
    for (int s = 64; s > 0; s >>= 1) {
        if (tid < s) {
            rA[tid] += rA[tid + s]; rB[tid] += rB[tid + s];
            rC[tid] += rC[tid + s]; rD[tid] += rD[tid + s];
        }
        __syncthreads();
    }
    if (tid == 0) {
        const double denom = (double)NN * (double)(NN - 1);
        out[0] = (float)(g_vt_sum / denom);
        out[1] = (float)(g_tv_sum / denom);
        out[2] = (float)rA[0] / (float)NN;
        out[3] = (float)rB[0] / (float)NN;
        out[4] = (float)rC[0] / (float)NN;
        out[5] = (float)rD[0] / (float)NN;
    }
}

// ---------------------------------------------------------------------------
typedef CUresult (*EncodeFn)(CUtensorMap*, CUtensorMapDataType, unsigned int,
                             void*, const unsigned long long*,
                             const unsigned long long*, const unsigned int*,
                             const unsigned int*, CUtensorMapInterleave,
                             CUtensorMapSwizzle, CUtensorMapL2promotion,
                             CUtensorMapFloatOOBfill);

static void encode_map(EncodeFn enc, CUtensorMap* m, void* ptr, unsigned rows) {
    unsigned long long dims[2]    = {DD, NN};
    unsigned long long strides[1] = {DD * sizeof(__nv_bfloat16)};
    unsigned int box[2]           = {64, rows};
    unsigned int es[2]            = {1, 1};
    enc(m, CU_TENSOR_MAP_DATA_TYPE_BFLOAT16, 2, ptr, dims, strides, box, es,
        CU_TENSOR_MAP_INTERLEAVE_NONE, CU_TENSOR_MAP_SWIZZLE_128B,
        CU_TENSOR_MAP_L2_PROMOTION_L2_128B, CU_TENSOR_MAP_FLOAT_OOB_FILL_NONE);
}

extern "C" void kernel_launch(void* const* d_in, const int* in_sizes, int n_in,
                              void* d_out, int out_size) {
    (void)in_sizes; (void)n_in; (void)out_size;
    const float* V = (const float*)d_in[0];
    const float* T = (const float*)d_in[1];
    float* out = (float*)d_out;

    void *pVhi, *pVlo, *pThi, *pTlo;
    cudaGetSymbolAddress(&pVhi, g_Vhi);
    cudaGetSymbolAddress(&pVlo, g_Vlo);
    cudaGetSymbolAddress(&pThi, g_Thi);
    cudaGetSymbolAddress(&pTlo, g_Tlo);

    void* sym = nullptr;
    cudaDriverEntryPointQueryResult qr;
    cudaGetDriverEntryPointByVersion("cuTensorMapEncodeTiled", &sym, 12000,
                                     cudaEnableDefault, &qr);
    EncodeFn enc = (EncodeFn)sym;

    CUtensorMap mVhi, mVlo, mThi, mTlo;
    encode_map(enc, &mVhi, pVhi, TM);   // A tiles: 128 rows
    encode_map(enc, &mVlo, pVlo, TM);
    encode_map(enc, &mThi, pThi, TN);   // B tiles: 256 rows
    encode_map(enc, &mTlo, pTlo, TN);

    cudaFuncSetAttribute(gemm_tc_kernel,
                         cudaFuncAttributeMaxDynamicSharedMemorySize, SMEM_DYN);

    init_kernel<<<NN * 32 / 256, 256>>>(V, T);
    gemm_tc_kernel<<<NCTA, NTHREADS, SMEM_DYN>>>(
        mVhi, mVlo, mThi, mTlo, V, T, out);
}

// round 7
// speedup vs baseline: 3.6687x; 1.7947x over previous
#include <cuda_runtime.h>
#include <cuda_bf16.h>
#include <cuda.h>
#include <stdint.h>

#define NN 4096
#define DD 256
#define MARGIN 0.1f
#define EPS 0.005f

#if defined(__CUDA_ARCH_FEAT_SM103_ALL) || defined(__CUDA_ARCH_FEAT_SM100_ALL)
#define HAS_TCGEN05 1
#else
#define HAS_TCGEN05 0
#endif

// idesc kind::f16: dtype=F32, atype=btype=BF16, N=256, M=128 (cg1)
#define IDESC 0x08400490u

// tile geometry
#define TM 128
#define TN 256
#define TILES_X (NN / TN)            // 16
#define TILES_Y (NN / TM)            // 32
#define NTILES  (TILES_X * TILES_Y)  // 512
#define NCTA    148
#define NTHREADS 544                 // 16 consumer warps + 1 producer warp

// stage layout (bytes): Ahi 16K | Alo 16K | Bhi 32K | Blo 32K
#define ST_ALO   16384
#define ST_BHI   32768
#define ST_BLO   65536
#define ST_BYTES 98304
#define OFF_TMEMP  (2 * ST_BYTES)         // 196608
#define OFF_MB     (OFF_TMEMP + 16)       // 196624 (8 mbarriers)
#define OFF_DC     (OFF_TMEMP + 128)      // 196736 (2 x 256 floats)
#define SMEM_DYN   (OFF_DC + 2048 + 1024)

typedef unsigned long long u64;

// ---- device-global scratch ----
__device__ double g_vt_sum;
__device__ double g_tv_sum;
__device__ unsigned g_done;
__device__ int    g_cnt[NN];
__device__ float  g_diag[NN];
__device__ __align__(1024) __nv_bfloat16 g_Vhi[NN * DD];
__device__ __align__(1024) __nv_bfloat16 g_Vlo[NN * DD];
__device__ __align__(1024) __nv_bfloat16 g_Thi[NN * DD];
__device__ __align__(1024) __nv_bfloat16 g_Tlo[NN * DD];

// ======================= PTX helpers =======================
__device__ __forceinline__ uint32_t smem_u32(const void* p) {
    uint32_t a;
    asm("{ .reg .u64 t; cvta.to.shared.u64 t, %1; cvt.u32.u64 %0, t; }"
        : "=r"(a) : "l"(p));
    return a;
}

#define MBARRIER_INIT(addr, cnt) \
    asm volatile("mbarrier.init.shared.b64 [%0], %1;" \
        :: "r"((uint32_t)(addr)), "r"((uint32_t)(cnt)) : "memory")

#define MBARRIER_EXPECT_TX(addr, bytes) \
    asm volatile("mbarrier.arrive.expect_tx.shared.b64 _, [%0], %1;" \
        :: "r"((uint32_t)(addr)), "r"((uint32_t)(bytes)) : "memory")

#define MBARRIER_ARRIVE(addr) \
    asm volatile("mbarrier.arrive.shared.b64 _, [%0];" \
        :: "r"((uint32_t)(addr)) : "memory")

#define MBARRIER_WAIT_PARITY(addr, parity) do {                                   \
    uint32_t _mb = (uint32_t)(addr);                                              \
    uint32_t _ph = (uint32_t)(parity);                                            \
    uint32_t _done;                                                               \
    asm volatile("{\n\t.reg .pred p;\n\t"                                         \
        "mbarrier.try_wait.parity.acquire.cta.shared::cta.b64 p, [%1], %2;\n\t"   \
        "selp.b32 %0, 1, 0, p;\n\t}"                                              \
        : "=r"(_done) : "r"(_mb), "r"(_ph) : "memory");                           \
    if (!_done) {                                                                 \
        asm volatile("{\n\t.reg .pred P1;\n\t"                                    \
            "W_%=:\n\t"                                                           \
            "mbarrier.try_wait.parity.acquire.cta.shared::cta.b64 P1, [%0], %1, 0x989680;\n\t" \
            "@P1 bra.uni D_%=;\n\t"                                               \
            "bra.uni W_%=;\n\t"                                                   \
            "D_%=:\n\t}"                                                          \
            :: "r"(_mb), "r"(_ph) : "memory");                                    \
    }                                                                             \
} while (0)

#if HAS_TCGEN05
#define TCGEN05_ALLOC(res_addr, ncols) \
    asm volatile("tcgen05.alloc.cta_group::1.sync.aligned.shared::cta.b32 [%0], %1;" \
        :: "r"((uint32_t)(res_addr)), "r"((uint32_t)(ncols)) : "memory")
#define TCGEN05_RELINQ() \
    asm volatile("tcgen05.relinquish_alloc_permit.cta_group::1.sync.aligned;")
#define TCGEN05_DEALLOC(tmem, ncols) \
    asm volatile("tcgen05.dealloc.cta_group::1.sync.aligned.b32 %0, %1;" \
        :: "r"(tmem), "r"((uint32_t)(ncols)))
#define TCGEN05_COMMIT(mbar) \
    asm volatile("tcgen05.commit.cta_group::1.mbarrier::arrive::one.shared::cluster.b64 [%0];" \
        :: "r"((uint32_t)(mbar)) : "memory")
#define TCGEN05_FENCE_AFTER() \
    asm volatile("tcgen05.fence::after_thread_sync;" ::: "memory")
#define TCGEN05_FENCE_BEFORE() \
    asm volatile("tcgen05.fence::before_thread_sync;" ::: "memory")
#define TCGEN05_WAIT_LD() \
    asm volatile("tcgen05.wait::ld.sync.aligned;" ::: "memory")

#define TCGEN05_LD_X32(r, addr) \
    asm volatile("tcgen05.ld.sync.aligned.32x32b.x32.b32 " \
        "{%0, %1, %2, %3, %4, %5, %6, %7, %8, %9, %10, %11, %12, %13, %14, %15, " \
        " %16, %17, %18, %19, %20, %21, %22, %23, %24, %25, %26, %27, %28, %29, %30, %31}, [%32];" \
        : "=r"((r)[0]),  "=r"((r)[1]),  "=r"((r)[2]),  "=r"((r)[3]),  \
          "=r"((r)[4]),  "=r"((r)[5]),  "=r"((r)[6]),  "=r"((r)[7]),  \
          "=r"((r)[8]),  "=r"((r)[9]),  "=r"((r)[10]), "=r"((r)[11]), \
          "=r"((r)[12]), "=r"((r)[13]), "=r"((r)[14]), "=r"((r)[15]), \
          "=r"((r)[16]), "=r"((r)[17]), "=r"((r)[18]), "=r"((r)[19]), \
          "=r"((r)[20]), "=r"((r)[21]), "=r"((r)[22]), "=r"((r)[23]), \
          "=r"((r)[24]), "=r"((r)[25]), "=r"((r)[26]), "=r"((r)[27]), \
          "=r"((r)[28]), "=r"((r)[29]), "=r"((r)[30]), "=r"((r)[31]) \
        : "r"(addr))

// SW128 SMEM descriptor: layout=SW128(2), version=1, SBO=64, LBO=1
static __device__ __forceinline__ uint64_t make_desc(uint32_t addr) {
    const uint64_t BASE =
        (uint64_t(2)  << 61) | (uint64_t(1) << 46) |
        (uint64_t(64) << 32) | (uint64_t(1) << 16);
    return BASE | ((uint64_t)(addr >> 4) & 0x3FFF);
}

__device__ __forceinline__ void tma_ld_2d(uint32_t dst, const void* map,
                                          int cx, int cy, uint32_t mbar) {
    asm volatile(
        "cp.async.bulk.tensor.2d.shared::cta.global.tile.mbarrier::complete_tx::bytes "
        "[%0], [%1, {%2, %3}], [%4];"
        :: "r"(dst), "l"(map), "r"(cx), "r"(cy), "r"(mbar) : "memory");
}

__device__ __forceinline__ void mma_f16_ss(uint32_t d, uint64_t da, uint64_t db,
                                           uint32_t en) {
    asm volatile("{\n\t.reg .pred p;\n\tsetp.ne.u32 p, %4, 0;\n\t"
        "tcgen05.mma.cta_group::1.kind::f16 [%0], %1, %2, %3, {%5, %5, %5, %5}, p;\n\t}"
        :: "r"(d), "l"(da), "l"(db), "r"(IDESC), "r"(en), "r"(0u) : "memory");
}
#endif  // HAS_TCGEN05

// ---------------------------------------------------------------------------
__device__ __forceinline__ void split4(float4 a, uint2& h, uint2& l) {
    __nv_bfloat162 hxy = __floats2bfloat162_rn(a.x, a.y);
    __nv_bfloat162 hzw = __floats2bfloat162_rn(a.z, a.w);
    float2 fxy = __bfloat1622float2(hxy);
    float2 fzw = __bfloat1622float2(hzw);
    __nv_bfloat162 lxy = __floats2bfloat162_rn(a.x - fxy.x, a.y - fxy.y);
    __nv_bfloat162 lzw = __floats2bfloat162_rn(a.z - fzw.x, a.w - fzw.y);
    h.x = reinterpret_cast<unsigned&>(hxy);
    h.y = reinterpret_cast<unsigned&>(hzw);
    l.x = reinterpret_cast<unsigned&>(lxy);
    l.y = reinterpret_cast<unsigned&>(lzw);
}

// ---------------------------------------------------------------------------
// Kernel 1: fused init — bf16 hi/lo split, exact fp32 diag, zero counters.
// ---------------------------------------------------------------------------
__global__ void init_kernel(const float* __restrict__ V,
                            const float* __restrict__ T) {
    const int gtid = blockIdx.x * blockDim.x + threadIdx.x;
    const int row  = gtid >> 5;
    const int lane = gtid & 31;
    if (gtid == 0) { g_vt_sum = 0.0; g_tv_sum = 0.0; g_done = 0u; }
    if (row >= NN) return;

    const float4* v4 = reinterpret_cast<const float4*>(V + (size_t)row * DD);
    const float4* t4 = reinterpret_cast<const float4*>(T + (size_t)row * DD);
    uint2* vh = reinterpret_cast<uint2*>(g_Vhi + (size_t)row * DD);
    uint2* vl = reinterpret_cast<uint2*>(g_Vlo + (size_t)row * DD);
    uint2* th = reinterpret_cast<uint2*>(g_Thi + (size_t)row * DD);
    uint2* tl = reinterpret_cast<uint2*>(g_Tlo + (size_t)row * DD);

    float acc = 0.f;
    #pragma unroll
    for (int p = 0; p < 2; p++) {
        const int idx = lane + p * 32;
        float4 a = v4[idx];
        float4 b = t4[idx];
        acc += a.x * b.x + a.y * b.y + a.z * b.z + a.w * b.w;
        uint2 h, l;
        split4(a, h, l); vh[idx] = h; vl[idx] = l;
        split4(b, h, l); th[idx] = h; tl[idx] = l;
    }
    #pragma unroll
    for (int off = 16; off > 0; off >>= 1)
        acc += __shfl_down_sync(0xFFFFFFFFu, acc, off);
    if (lane == 0) { g_diag[row] = acc; g_cnt[row] = 0; }
}

// ---------------------------------------------------------------------------
// Kernel 2: persistent warp-specialized tcgen05 GEMM + ranking epilogue +
// last-CTA finalize. 148 CTAs x 544 threads.
//   warps 0-15 : epilogue consumers — warp w: TMEM subpartition w&3
//                (rows (w&3)*32+lane), columns [(w>>2)*64, +64)
//   warp 16    : producer (thread 512 issues TMA + MMA)
// TMEM: two 256-col fp32 accumulator buffers, alternating per tile.
// ---------------------------------------------------------------------------
__global__ __launch_bounds__(NTHREADS, 1)
void gemm_tc_kernel(const __grid_constant__ CUtensorMap mVhi,
                    const __grid_constant__ CUtensorMap mVlo,
                    const __grid_constant__ CUtensorMap mThi,
                    const __grid_constant__ CUtensorMap mTlo,
                    const float* __restrict__ V,
                    const float* __restrict__ T,
                    float* __restrict__ out) {
    extern __shared__ char smem_raw[];
    const uint32_t raw  = smem_u32(smem_raw);
    const uint32_t base = (raw + 1023) & ~1023u;
    char* gbase = smem_raw + (base - raw);

    const int tid  = threadIdx.x;
    const int lane = tid & 31;
    const int cta  = blockIdx.x;
    const int ntiles = (NTILES - cta + NCTA - 1) / NCTA;

    float vt = 0.f, tv = 0.f;

#if HAS_TCGEN05
    const int wid = tid >> 5;
    const uint32_t S_TMEMP = base + OFF_TMEMP;
    const uint32_t MB_FULL = base + OFF_MB;        // +0, +8
    const uint32_t MB_EMPT = base + OFF_MB + 16;   // +16, +24
    const uint32_t MB_RES  = base + OFF_MB + 32;   // +32, +40
    const uint32_t MB_EPI  = base + OFF_MB + 48;   // +48, +56
    float* s_mdc = reinterpret_cast<float*>(gbase + OFF_DC);  // 2 x 256 floats

    if (wid == 16) {
        TCGEN05_ALLOC(S_TMEMP, 512);
        TCGEN05_RELINQ();
    }
    if (tid == 0) {
        MBARRIER_INIT(MB_FULL + 0, 1);
        MBARRIER_INIT(MB_FULL + 8, 1);
        MBARRIER_INIT(MB_EMPT + 0, 1);
        MBARRIER_INIT(MB_EMPT + 8, 1);
        MBARRIER_INIT(MB_RES  + 0, 1);
        MBARRIER_INIT(MB_RES  + 8, 1);
        MBARRIER_INIT(MB_EPI  + 0, 16);
        MBARRIER_INIT(MB_EPI  + 8, 16);
    }
    __syncthreads();
    uint32_t tmem;
    asm volatile("ld.shared.b32 %0, [%1];" : "=r"(tmem) : "r"(S_TMEMP));

    if (tid == 512) {
        // ---------------- producer ----------------
        const int nchunks = ntiles * 4;

        auto issue_tma = [&](int kk) {
            const int lt    = kk >> 2;
            const int chunk = kk & 3;
            const int s     = kk & 1;
            const int tile  = cta + lt * NCTA;
            const int row0  = (tile >> 4) * TM;
            const int col0  = (tile & 15) * TN;
            const uint32_t st = base + s * ST_BYTES;
            const uint32_t fb = MB_FULL + s * 8;
            MBARRIER_EXPECT_TX(fb, ST_BYTES);
            tma_ld_2d(st +      0, &mVhi, chunk * 64, row0, fb);
            tma_ld_2d(st + ST_ALO, &mVlo, chunk * 64, row0, fb);
            tma_ld_2d(st + ST_BHI, &mThi, chunk * 64, col0, fb);
            tma_ld_2d(st + ST_BLO, &mTlo, chunk * 64, col0, fb);
        };

        issue_tma(0);
        if (nchunks > 1) issue_tma(1);

        for (int kk = 0; kk < nchunks; kk++) {
            const int s     = kk & 1;
            const int lt    = kk >> 2;
            const int chunk = kk & 3;
            const int buf   = lt & 1;
            const uint32_t st = base + s * ST_BYTES;
            const uint32_t dbuf = tmem + buf * 256;

            MBARRIER_WAIT_PARITY(MB_FULL + s * 8, (kk >> 1) & 1);
            if (chunk == 0 && lt >= 2)
                MBARRIER_WAIT_PARITY(MB_EPI + buf * 8, ((lt - 2) >> 1) & 1);

            const uint64_t dAhi = make_desc(st);
            const uint64_t dAlo = make_desc(st + ST_ALO);
            const uint64_t dBhi = make_desc(st + ST_BHI);
            const uint64_t dBlo = make_desc(st + ST_BLO);
            #pragma unroll
            for (int ks = 0; ks < 4; ks++)
                mma_f16_ss(dbuf, dAhi + ks * 2, dBhi + ks * 2,
                           (chunk == 0 && ks == 0) ? 0u : 1u);
            #pragma unroll
            for (int ks = 0; ks < 4; ks++)
                mma_f16_ss(dbuf, dAhi + ks * 2, dBlo + ks * 2, 1u);
            #pragma unroll
            for (int ks = 0; ks < 4; ks++)
                mma_f16_ss(dbuf, dAlo + ks * 2, dBhi + ks * 2, 1u);

            TCGEN05_COMMIT(MB_EMPT + s * 8);
            if (chunk == 3) TCGEN05_COMMIT(MB_RES + buf * 8);

            if (kk + 2 < nchunks) {
                MBARRIER_WAIT_PARITY(MB_EMPT + s * 8, (kk >> 1) & 1);
                issue_tma(kk + 2);
            }
        }
    } else if (tid < 512) {
        // ---------------- consumers: 16 warps ----------------
        const int w   = wid;          // 0..15
        const int sub = w & 3;        // TMEM subpartition == SMSP
        const int ch  = w >> 2;       // 64-column chunk 0..3
        for (int lt = 0; lt < ntiles; lt++) {
            const int buf  = lt & 1;
            const int tile = cta + lt * NCTA;
            const int row0 = (tile >> 4) * TM;
            const int col0 = (tile & 15) * TN;
            const int r    = row0 + sub * 32 + lane;
            const float dr  = g_diag[r];
            const float mdr = MARGIN - dr;
            const uint32_t dbuf = tmem + buf * 256 + ch * 64;
            float* mdc = s_mdc + buf * 256 + ch * 64;
            int cnt = 0;

            MBARRIER_WAIT_PARITY(MB_RES + buf * 8, (lt >> 1) & 1);
            TCGEN05_FENCE_AFTER();

            // self-written per warp (redundant across subs; each warp reads
            // only what it wrote, so no cross-warp sync needed)
            mdc[lane]      = MARGIN - g_diag[col0 + ch * 64 + lane];
            mdc[lane + 32] = MARGIN - g_diag[col0 + ch * 64 + 32 + lane];

            #pragma unroll 1
            for (int g = 0; g < 2; g++) {
                uint32_t dreg[32];
                TCGEN05_LD_X32(dreg, dbuf + g * 32);
                TCGEN05_WAIT_LD();
                #pragma unroll
                for (int j = 0; j < 32; j++) {
                    const int cc = ch * 64 + g * 32 + j;
                    const int c  = col0 + cc;
                    const float sv = __uint_as_float(dreg[j]);
                    if (c != r) {
                        const float diff = sv - dr;
                        vt += fmaxf(sv + mdr, 0.f);
                        tv += fmaxf(sv + mdc[g * 32 + j], 0.f);
                        if (fabsf(diff) < EPS) {
                            const float4* a4 = reinterpret_cast<const float4*>(V + (size_t)r * DD);
                            const float4* b4 = reinterpret_cast<const float4*>(T + (size_t)c * DD);
                            float ex = 0.f;
                            #pragma unroll 8
                            for (int k = 0; k < DD / 4; k++) {
                                float4 x = a4[k], y = b4[k];
                                ex += x.x * y.x + x.y * y.y + x.z * y.z + x.w * y.w;
                            }
                            cnt += (ex > dr) ? 1 : 0;
                        } else {
                            cnt += (diff > 0.f) ? 1 : 0;
                        }
                    }
                }
            }
            TCGEN05_FENCE_BEFORE();
            if (lane == 0) MBARRIER_ARRIVE(MB_EPI + buf * 8);
            atomicAdd(&g_cnt[r], cnt);
        }
    }

    __syncthreads();
    if (wid == 16) TCGEN05_DEALLOC(tmem, 512);

#else  // ---------------- fallback: plain fp32 (not selected on GB300) -----
    (void)mVhi; (void)mVlo; (void)mThi; (void)mTlo;
    for (int lt = 0; lt < ntiles; lt++) {
        const int tile = cta + lt * NCTA;
        const int row0 = (tile >> 4) * TM;
        const int col0 = (tile & 15) * TN;
        if (tid < 128) {
            const int r = row0 + tid;
            const float dr = g_diag[r];
            const float4* a4 = reinterpret_cast<const float4*>(V + (size_t)r * DD);
            int cnt = 0;
            for (int cc = 0; cc < TN; cc++) {
                const int c = col0 + cc;
                if (c == r) continue;
                const float4* b4 = reinterpret_cast<const float4*>(T + (size_t)c * DD);
                float s = 0.f;
                #pragma unroll 8
                for (int k = 0; k < DD / 4; k++) {
                    float4 x = a4[k], y = b4[k];
                    s += x.x * y.x + x.y * y.y + x.z * y.z + x.w * y.w;
                }
                vt += fmaxf(0.f, MARGIN - dr + s);
                tv += fmaxf(0.f, MARGIN - g_diag[c] + s);
                cnt += (s > dr) ? 1 : 0;
            }
            atomicAdd(&g_cnt[r], cnt);
        }
    }
    __syncthreads();
#endif

    // loss reduction: one double atomic per warp
    #pragma unroll
    for (int off = 16; off > 0; off >>= 1) {
        vt += __shfl_down_sync(0xFFFFFFFFu, vt, off);
        tv += __shfl_down_sync(0xFFFFFFFFu, tv, off);
    }
    if (lane == 0) {
        atomicAdd(&g_vt_sum, (double)vt);
        atomicAdd(&g_tv_sum, (double)tv);
    }

    // ---- last-CTA finalize ----
    __shared__ unsigned s_last;
    __shared__ int rA[512], rB[512], rC[512], rD[512];
    __threadfence();
    __syncthreads();
    if (tid == 0) s_last = (atomicAdd(&g_done, 1u) == (unsigned)(NCTA - 1));
    __syncthreads();
    if (!s_last) return;

    if (tid < 512) {
        int c1 = 0, c5 = 0, c10 = 0, rs = 0;
        for (int i = tid; i < NN; i += 512) {
            int c = g_cnt[i];
            c1  += (c < 1);
            c5  += (c < 5);
            c10 += (c < 10);
            rs  += c;
        }
        rA[tid] = c1; rB[tid] = c5; rC[tid] = c10; rD[tid] = rs;
    }
    __syncthreads();
    for (int s = 256; s > 0; s >>= 1) {
        if (tid < s) {
            rA[tid] += rA[tid + s]; rB[tid] += rB[tid + s];
            rC[tid] += rC[tid + s]; rD[tid] += rD[tid + s];
        }
        __syncthreads();
    }
    if (tid == 0) {
        const double denom = (double)NN * (double)(NN - 1);
        out[0] = (float)(g_vt_sum / denom);
        out[1] = (float)(g_tv_sum / denom);
        out[2] = (float)rA[0] / (float)NN;
        out[3] = (float)rB[0] / (float)NN;
        out[4] = (float)rC[0] / (float)NN;
        out[5] = (float)rD[0] / (float)NN;
    }
}

// ---------------------------------------------------------------------------
typedef CUresult (*EncodeFn)(CUtensorMap*, CUtensorMapDataType, unsigned int,
                             void*, const unsigned long long*,
                             const unsigned long long*, const unsigned int*,
                             const unsigned int*, CUtensorMapInterleave,
                             CUtensorMapSwizzle, CUtensorMapL2promotion,
                             CUtensorMapFloatOOBfill);

static void encode_map(EncodeFn enc, CUtensorMap* m, void* ptr, unsigned rows) {
    unsigned long long dims[2]    = {DD, NN};
    unsigned long long strides[1] = {DD * sizeof(__nv_bfloat16)};
    unsigned int box[2]           = {64, rows};
    unsigned int es[2]            = {1, 1};
    enc(m, CU_TENSOR_MAP_DATA_TYPE_BFLOAT16, 2, ptr, dims, strides, box, es,
        CU_TENSOR_MAP_INTERLEAVE_NONE, CU_TENSOR_MAP_SWIZZLE_128B,
        CU_TENSOR_MAP_L2_PROMOTION_L2_128B, CU_TENSOR_MAP_FLOAT_OOB_FILL_NONE);
}

extern "C" void kernel_launch(void* const* d_in, const int* in_sizes, int n_in,
                              void* d_out, int out_size) {
    (void)in_sizes; (void)n_in; (void)out_size;
    const float* V = (const float*)d_in[0];
    const float* T = (const float*)d_in[1];
    float* out = (float*)d_out;

    void *pVhi, *pVlo, *pThi, *pTlo;
    cudaGetSymbolAddress(&pVhi, g_Vhi);
    cudaGetSymbolAddress(&pVlo, g_Vlo);
    cudaGetSymbolAddress(&pThi, g_Thi);
    cudaGetSymbolAddress(&pTlo, g_Tlo);

    void* sym = nullptr;
    cudaDriverEntryPointQueryResult qr;
    cudaGetDriverEntryPointByVersion("cuTensorMapEncodeTiled", &sym, 12000,
                                     cudaEnableDefault, &qr);
    EncodeFn enc = (EncodeFn)sym;

    CUtensorMap mVhi, mVlo, mThi, mTlo;
    encode_map(enc, &mVhi, pVhi, TM);   // A tiles: 128 rows
    encode_map(enc, &mVlo, pVlo, TM);
    encode_map(enc, &mThi, pThi, TN);   // B tiles: 256 rows
    encode_map(enc, &mTlo, pTlo, TN);

    cudaFuncSetAttribute(gemm_tc_kernel,
                         cudaFuncAttributeMaxDynamicSharedMemorySize, SMEM_DYN);

    init_kernel<<<NN * 32 / 256, 256>>>(V, T);
    gemm_tc_kernel<<<NCTA, NTHREADS, SMEM_DYN>>>(
        mVhi, mVlo, mThi, mTlo, V, T, out);
}